// round 13
// baseline (speedup 1.0000x reference)
#include <cuda_runtime.h>
#include <cuda_bf16.h>
#include <cuda.h>
#include <math.h>
#include <stdint.h>

// ---------------------------------------------------------------------------
// AFNO block. LN/fftW SIMT fp32 (fftW also computes the Nyquist row inline).
// fftH (fwd+inv), ifftW, block-diag mix, and MLP all on tcgen05 bf16 hi/lo
// (3-term) via the proven K-major SS path. Transposed-GEMM formulation for
// the spectral kernels (coalesced epilogues).
// ---------------------------------------------------------------------------

#if defined(__CUDA_ARCH__) && (defined(__CUDA_ARCH_FEAT_SM103_ALL) || \
    defined(__CUDA_ARCH_FEAT_SM100_ALL) || defined(__CUDA_ARCH_FEAT_SM101_ALL))
#define TC_OK 1
#else
#define TC_OK 0
#endif

#define Hdim   128
#define Wdim   256
#define WFdim  129
#define Ddim   768
#define NBv    8
#define BSv    96
#define HIDv   3072
#define TOKENS 65536
#define NPOSv  33024
#define LAMv   0.01f
#define CKP    192

// -------------------- scratch (device globals; no allocation) ---------------
__device__ float g_P [(size_t)TOKENS * Ddim];
__device__ float g_T [(size_t)TOKENS * Ddim];
__device__ float g_Yr[(size_t)NPOSv * Ddim];
__device__ float g_Yi[(size_t)NPOSv * Ddim];
__device__ float g_Zr[(size_t)NPOSv * Ddim];
__device__ float g_Zi[(size_t)NPOSv * Ddim];
__device__ float g_Ar[(size_t)NPOSv * Ddim];
__device__ float g_Ai[(size_t)NPOSv * Ddim];
// bf16 hi/lo operands for tensor-core MLP
__device__ __align__(1024) __nv_bfloat16 gA_hi[(size_t)TOKENS * Ddim];
__device__ __align__(1024) __nv_bfloat16 gA_lo[(size_t)TOKENS * Ddim];
__device__ __align__(1024) __nv_bfloat16 gH_hi[(size_t)TOKENS * HIDv];
__device__ __align__(1024) __nv_bfloat16 gH_lo[(size_t)TOKENS * HIDv];
__device__ __align__(1024) __nv_bfloat16 gW1T_hi[(size_t)HIDv * Ddim];
__device__ __align__(1024) __nv_bfloat16 gW1T_lo[(size_t)HIDv * Ddim];
__device__ __align__(1024) __nv_bfloat16 gW2T_hi[(size_t)Ddim * HIDv];
__device__ __align__(1024) __nv_bfloat16 gW2T_lo[(size_t)Ddim * HIDv];
// DFT tables
__device__ float g_FcT[Wdim * WFdim], g_FsT[Wdim * WFdim];   // fp32 [w][wf] (fftW SIMT)
__device__ __align__(16) __nv_bfloat16 tGc_h [Hdim * Hdim], tGc_l [Hdim * Hdim];
__device__ __align__(16) __nv_bfloat16 tGsP_h[Hdim * Hdim], tGsP_l[Hdim * Hdim];
__device__ __align__(16) __nv_bfloat16 tGsM_h[Hdim * Hdim], tGsM_l[Hdim * Hdim];
__device__ __align__(16) __nv_bfloat16 tCr_h [Wdim * CKP],  tCr_l [Wdim * CKP];
__device__ __align__(16) __nv_bfloat16 tCi_h [Wdim * CKP],  tCi_l [Wdim * CKP];

// -------------------- PTX helpers -------------------------------------------
__device__ __forceinline__ uint32_t smem_u32(const void* p) {
    uint32_t a;
    asm("{ .reg .u64 t; cvta.to.shared.u64 t, %1; cvt.u32.u64 %0, t; }" : "=r"(a) : "l"(p));
    return a;
}
#define MBAR_INIT(a, c) \
    asm volatile("mbarrier.init.shared.b64 [%0], %1;" :: "r"(a), "r"(c) : "memory")
#define MBAR_EXPECT_TX(a, b) \
    asm volatile("mbarrier.arrive.expect_tx.shared.b64 _, [%0], %1;" :: "r"(a), "r"(b) : "memory")
#define MBAR_WAIT(a, ph) do { \
    uint32_t _m = (a), _p = (ph), _d; \
    asm volatile("{\n\t.reg .pred p;\n\t" \
        "mbarrier.try_wait.parity.acquire.cta.shared::cta.b64 p, [%1], %2;\n\t" \
        "selp.b32 %0, 1, 0, p;\n\t}" : "=r"(_d) : "r"(_m), "r"(_p) : "memory"); \
    if (!_d) { asm volatile("{\n\t.reg .pred P1;\n\tWL%=:\n\t" \
        "mbarrier.try_wait.parity.acquire.cta.shared::cta.b64 P1, [%0], %1, 0x989680;\n\t" \
        "@P1 bra.uni WD%=;\n\tbra.uni WL%=;\n\tWD%=:\n\t}" :: "r"(_m), "r"(_p) : "memory"); } \
} while(0)
#define MBAR_WAIT_RELAXED(a, ph) do { \
    uint32_t _m = (a), _p = (ph), _d; \
    asm volatile("{\n\t.reg .pred p;\n\t" \
        "mbarrier.try_wait.parity.relaxed.cta.shared::cta.b64 p, [%1], %2, 0x989680;\n\t" \
        "selp.b32 %0, 1, 0, p;\n\t}" : "=r"(_d) : "r"(_m), "r"(_p) : "memory"); \
    if (!_d) { asm volatile("{\n\t.reg .pred P1;\n\tWL%=:\n\t" \
        "mbarrier.try_wait.parity.relaxed.cta.shared::cta.b64 P1, [%0], %1, 0x989680;\n\t" \
        "@P1 bra.uni WD%=;\n\tbra.uni WL%=;\n\tWD%=:\n\t}" :: "r"(_m), "r"(_p) : "memory"); } \
} while(0)
#define TMA_LOAD_2D(dst, map, cx, cy, mbar) \
    asm volatile("cp.async.bulk.tensor.2d.shared::cta.global.tile.mbarrier::complete_tx::bytes " \
        "[%0], [%1, {%2, %3}], [%4];" \
        :: "r"(dst), "l"(map), "r"(cx), "r"(cy), "r"(mbar) : "memory")
#define TC_ALLOC(sm, n) \
    asm volatile("tcgen05.alloc.cta_group::1.sync.aligned.shared::cta.b32 [%0], %1;" \
        :: "r"(sm), "r"(n) : "memory")
#define TC_DEALLOC(t, n) \
    asm volatile("tcgen05.dealloc.cta_group::1.sync.aligned.b32 %0, %1;" :: "r"(t), "r"(n))
#define TC_COMMIT(mbar) \
    asm volatile("tcgen05.commit.cta_group::1.mbarrier::arrive::one.shared::cluster.b64 [%0];" \
        :: "r"(mbar) : "memory")
#define TC_FENCE_AFTER() asm volatile("tcgen05.fence::after_thread_sync;" ::: "memory")
#define TC_WAIT_LD() asm volatile("tcgen05.wait::ld.sync.aligned;" ::: "memory")
#define FENCE_ASYNC() asm volatile("fence.proxy.async.shared::cta;" ::: "memory")
#define TC_LD_X32(r, addr) \
    asm volatile("tcgen05.ld.sync.aligned.32x32b.x32.b32 " \
        "{%0,%1,%2,%3,%4,%5,%6,%7,%8,%9,%10,%11,%12,%13,%14,%15," \
        "%16,%17,%18,%19,%20,%21,%22,%23,%24,%25,%26,%27,%28,%29,%30,%31}, [%32];" \
        : "=r"((r)[0]),"=r"((r)[1]),"=r"((r)[2]),"=r"((r)[3]),"=r"((r)[4]),"=r"((r)[5]), \
          "=r"((r)[6]),"=r"((r)[7]),"=r"((r)[8]),"=r"((r)[9]),"=r"((r)[10]),"=r"((r)[11]), \
          "=r"((r)[12]),"=r"((r)[13]),"=r"((r)[14]),"=r"((r)[15]),"=r"((r)[16]),"=r"((r)[17]), \
          "=r"((r)[18]),"=r"((r)[19]),"=r"((r)[20]),"=r"((r)[21]),"=r"((r)[22]),"=r"((r)[23]), \
          "=r"((r)[24]),"=r"((r)[25]),"=r"((r)[26]),"=r"((r)[27]),"=r"((r)[28]),"=r"((r)[29]), \
          "=r"((r)[30]),"=r"((r)[31]) : "r"(addr))

__device__ __forceinline__ void mma_f16_ss(uint32_t d, uint64_t ad, uint64_t bd,
                                           uint32_t idesc, uint32_t en) {
#if TC_OK
    asm volatile("{\n\t.reg .pred p;\n\tsetp.ne.u32 p, %4, 0;\n\t"
        "tcgen05.mma.cta_group::1.kind::f16 [%0], %1, %2, %3, {%5, %5, %5, %5}, p;\n\t}"
        :: "r"(d), "l"(ad), "l"(bd), "r"(idesc), "r"(en), "r"(0u) : "memory");
#endif
}
// K-major SW128 desc (LBO=1, SBO=64) — the proven layout
__device__ __forceinline__ uint64_t smem_desc(uint32_t addr) {
    return ((uint64_t)2 << 61) | ((uint64_t)1 << 46) | ((uint64_t)64 << 32)
         | ((uint64_t)1 << 16) | (uint64_t)((addr >> 4) & 0x3FFF);
}
__device__ __forceinline__ void split2(float v, __nv_bfloat16* h, __nv_bfloat16* l) {
    *h = __float2bfloat16_rn(v);
    *l = __float2bfloat16_rn(v - __bfloat162float(*h));
}
__device__ __forceinline__ uint32_t pack2(float v0, float v1, int lo) {
    __nv_bfloat16 h0, l0, h1, l1;
    split2(v0, &h0, &l0); split2(v1, &h1, &l1);
    __nv_bfloat16 a = lo ? l0 : h0, b = lo ? l1 : h1;
    return (uint32_t)__bfloat16_as_ushort(a) | ((uint32_t)__bfloat16_as_ushort(b) << 16);
}
#define SWZ(x) ((x) ^ (((x) >> 3) & 0x70))

#define IDESC_BF16 ((1u << 4) | (1u << 7) | (1u << 10) | (16u << 17) | (8u << 24))
#define IDESC_N256 ((1u << 4) | (1u << 7) | (1u << 10) | (32u << 17) | (8u << 24))
#define IDESC_N96  ((1u << 4) | (1u << 7) | (1u << 10) | (12u << 17) | (8u << 24))

// -------------------- DFT table init ----------------------------------------
__global__ void k_init() {
    int i = blockIdx.x * 256 + threadIdx.x;
    const double PI2 = 6.283185307179586476925286766559;
    const double S = sqrt(32768.0);
    if (i < Wdim * WFdim) {
        int w = i / WFdim, wf = i % WFdim;
        double th = PI2 * (double)((wf * w) % Wdim) / (double)Wdim;
        g_FcT[i] = (float)( cos(th) / S);
        g_FsT[i] = (float)(-sin(th) / S);
    }
    if (i < Hdim * Hdim) {
        int m = i >> 7, k = i & 127;
        double ph = PI2 * (double)((m * k) % Hdim) / (double)Hdim;
        float cv = (float)cos(ph), sv = (float)sin(ph);
        split2(cv,  &tGc_h[i],  &tGc_l[i]);
        split2(sv,  &tGsP_h[i], &tGsP_l[i]);
        split2(-sv, &tGsM_h[i], &tGsM_l[i]);
    }
    if (i < Wdim * CKP) {
        int w = i / CKP, wf = i % CKP;
        float cr = 0.f, ci = 0.f;
        if (wf < WFdim) {
            double th = PI2 * (double)((wf * w) % Wdim) / (double)Wdim;
            double a = (wf == 0 || wf == Wdim / 2) ? 1.0 : 2.0;
            cr = (float)( a * cos(th) / S);
            ci = (float)(-a * sin(th) / S);
        }
        split2(cr, &tCr_h[i], &tCr_l[i]);
        split2(ci, &tCi_h[i], &tCi_l[i]);
    }
}

// -------------------- LayerNorm (SPLIT=1: emit bf16 hi/lo) -------------------
template <int SPLIT>
__global__ void k_ln(const float* __restrict__ in, const float* __restrict__ gam,
                     const float* __restrict__ bet, float* __restrict__ out,
                     __nv_bfloat16* __restrict__ ohi, __nv_bfloat16* __restrict__ olo) {
    int t = blockIdx.x;
    const float* xp = in + (size_t)t * Ddim;
    int tid = threadIdx.x;
    float v[3], s = 0.f, s2 = 0.f;
#pragma unroll
    for (int i = 0; i < 3; i++) { v[i] = xp[tid + i * 256]; s += v[i]; s2 += v[i] * v[i]; }
#pragma unroll
    for (int o = 16; o; o >>= 1) {
        s  += __shfl_xor_sync(0xffffffffu, s,  o);
        s2 += __shfl_xor_sync(0xffffffffu, s2, o);
    }
    __shared__ float sh[2][8];
    __shared__ float mu_s, rs_s;
    int w = tid >> 5;
    if ((tid & 31) == 0) { sh[0][w] = s; sh[1][w] = s2; }
    __syncthreads();
    if (tid == 0) {
        float ts = 0.f, ts2 = 0.f;
#pragma unroll
        for (int i = 0; i < 8; i++) { ts += sh[0][i]; ts2 += sh[1][i]; }
        float mu = ts * (1.f / 768.f);
        float var = ts2 * (1.f / 768.f) - mu * mu;
        mu_s = mu; rs_s = rsqrtf(var + 1e-5f);
    }
    __syncthreads();
    float mu = mu_s, rs = rs_s;
#pragma unroll
    for (int i = 0; i < 3; i++) {
        int c = tid + i * 256;
        float r = (v[i] - mu) * rs * gam[c] + bet[c];
        if (SPLIT == 0) {
            out[(size_t)t * Ddim + c] = r;
        } else {
            __nv_bfloat16 hi, lo;
            split2(r, &hi, &lo);
            ohi[(size_t)t * Ddim + c] = hi;
            olo[(size_t)t * Ddim + c] = lo;
        }
    }
}

// -------------------- transpose + split weights ------------------------------
__global__ void k_splitT(const float* __restrict__ in, __nv_bfloat16* __restrict__ oh,
                         __nv_bfloat16* __restrict__ ol, int R, int C) {
    __shared__ float t[32][33];
    int c0 = blockIdx.x * 32, r0 = blockIdx.y * 32;
    int x = threadIdx.x, y = threadIdx.y;
#pragma unroll
    for (int i = 0; i < 32; i += 8)
        t[y + i][x] = in[(size_t)(r0 + y + i) * C + c0 + x];
    __syncthreads();
#pragma unroll
    for (int i = 0; i < 32; i += 8) {
        __nv_bfloat16 hi, lo;
        split2(t[x][y + i], &hi, &lo);
        size_t o = (size_t)(c0 + y + i) * R + r0 + x;
        oh[o] = hi; ol[o] = lo;
    }
}

// -------------------- rfft along W: wf 0..127 + inline Nyquist ---------------
__global__ void __launch_bounds__(256, 2) k_fftW(const float* __restrict__ X) {
    int bh = blockIdx.z; int b = bh >> 7; int h = bh & 127;
    int n0 = blockIdx.x * 64;
    const float* B = X + ((size_t)(b * 32768 + h * 256)) * Ddim;
    __shared__ float Ac[16][128], As[16][128], Bs[16][64];
    int tid = threadIdx.x, tx = tid & 15, ty = tid >> 4;
    float accr[8][4] = {}, acci[8][4] = {};
    float nyq = 0.f;
    for (int k0 = 0; k0 < Wdim; k0 += 16) {
#pragma unroll
        for (int i = 0; i < 8; i++) {
            int e = tid + i * 256; int k = e >> 7, m = e & 127;
            Ac[k][m] = g_FcT[(k0 + k) * WFdim + m];
            As[k][m] = g_FsT[(k0 + k) * WFdim + m];
        }
#pragma unroll
        for (int i = 0; i < 4; i++) {
            int e = tid + i * 256; int k = e >> 6, n = e & 63;
            float v = B[(size_t)(k0 + k) * Ddim + n0 + n];
            Bs[k][n] = v;
            nyq += ((k0 + k) & 1) ? -v : v;
        }
        __syncthreads();
#pragma unroll
        for (int kk = 0; kk < 16; kk++) {
            float a0[8], a1[8], bb[4];
#pragma unroll
            for (int i = 0; i < 8; i++) { a0[i] = Ac[kk][ty * 8 + i]; a1[i] = As[kk][ty * 8 + i]; }
#pragma unroll
            for (int j = 0; j < 4; j++) bb[j] = Bs[kk][tx * 4 + j];
#pragma unroll
            for (int i = 0; i < 8; i++)
#pragma unroll
                for (int j = 0; j < 4; j++) {
                    accr[i][j] += a0[i] * bb[j];
                    acci[i][j] += a1[i] * bb[j];
                }
        }
        __syncthreads();
    }
#pragma unroll
    for (int i = 0; i < 8; i++) {
        int gm = ty * 8 + i;
        size_t base = ((size_t)((b * WFdim + gm) * Hdim + h)) * Ddim + n0 + tx * 4;
#pragma unroll
        for (int j = 0; j < 4; j++) { g_Yr[base + j] = accr[i][j]; g_Yi[base + j] = acci[i][j]; }
    }
    // Nyquist row wf=128: sum (-1)^w x[w,d] / S. Each (w,n) loaded exactly once.
    float* red = &Ac[0][0];
    __syncthreads();
    red[tid] = nyq;
    __syncthreads();
    if (tid < 64) {
        float s = red[tid] + red[tid + 64] + red[tid + 128] + red[tid + 192];
        size_t base = ((size_t)((b * WFdim + 128) * Hdim + h)) * Ddim + n0 + tid;
        g_Yr[base] = s * (1.f / 181.01933598375617f);
        g_Yi[base] = 0.f;
    }
}

// -------------------- tensorized complex FFT along H (transposed GEMM) -------
#define FH_A0   1024
#define FH_B0   (1024 + 4 * 16384)
#define FH_SMEM (FH_B0 + 6 * 16384)
template <int INV>
__global__ void __launch_bounds__(256, 1) k_fftH_tc() {
#if TC_OK
    extern __shared__ char smem[];
    uint32_t sb = smem_u32(smem);
    int tid = threadIdx.x, wid = tid >> 5, lane = tid & 31;
    int z = blockIdx.y; int b = z / WFdim; int wf = z % WFdim;
    int d0 = blockIdx.x * 128;
    size_t slab = (size_t)(b * WFdim + wf) * Hdim * Ddim;
    const float* Br = (INV == 0) ? (g_Yr + slab) : (g_Zr + slab);
    const float* Bi = (INV == 0) ? (g_Yi + slab) : (g_Zi + slab);
    float* Or = (INV == 0) ? g_Zr : g_Ar;
    float* Oi = (INV == 0) ? g_Zi : g_Ai;
    size_t outBase = (INV == 0) ? slab : ((size_t)b * Hdim * WFdim + wf) * Ddim;
    size_t outStride = (INV == 0) ? (size_t)Ddim : (size_t)WFdim * Ddim;

    if (wid == 0) TC_ALLOC(sb, 256);
    if (tid == 0) MBAR_INIT(sb + 8, 1);
    __syncthreads();
    uint32_t tmem;
    asm volatile("ld.shared.b32 %0, [%1];" : "=r"(tmem) : "r"(sb));

    const __nv_bfloat16* gsrc[6] = {tGc_h, tGc_l, tGsP_h, tGsP_l, tGsM_h, tGsM_l};

    for (int c = 0; c < 2; c++) {
        int k0 = c * 64;
        for (int idx = tid; idx < 4096; idx += 256) {
            int hp = idx >> 7, d = idx & 127;
            int h = hp * 2;
            size_t g0 = (size_t)(k0 + h) * Ddim + d0 + d;
            float r0 = Br[g0], r1 = Br[g0 + Ddim];
            float i0 = Bi[g0], i1 = Bi[g0 + Ddim];
            uint32_t sw = SWZ((uint32_t)(d * 128 + h * 2));
            *(uint32_t*)(smem + FH_A0 + sw)         = pack2(r0, r1, 0);
            *(uint32_t*)(smem + FH_A0 + 16384 + sw) = pack2(r0, r1, 1);
            *(uint32_t*)(smem + FH_A0 + 32768 + sw) = pack2(i0, i1, 0);
            *(uint32_t*)(smem + FH_A0 + 49152 + sw) = pack2(i0, i1, 1);
        }
        for (int idx = tid; idx < 6144; idx += 256) {
            int t = idx >> 10, r = idx & 1023, m = r >> 3, u = r & 7;
            uint4 v = *(const uint4*)(gsrc[t] + m * Hdim + k0 + u * 8);
            *(uint4*)(smem + FH_B0 + t * 16384 + SWZ((uint32_t)(m * 128 + u * 16))) = v;
        }
        FENCE_ASYNC();
        __syncthreads();
        if (tid == 0) {
            uint64_t aRh = smem_desc(sb + FH_A0),         aRl = smem_desc(sb + FH_A0 + 16384);
            uint64_t aIh = smem_desc(sb + FH_A0 + 32768), aIl = smem_desc(sb + FH_A0 + 49152);
            uint64_t bCh = smem_desc(sb + FH_B0),         bCl = smem_desc(sb + FH_B0 + 16384);
            uint32_t s1 = (INV == 0) ? 2u : 4u;
            uint32_t s2 = (INV == 0) ? 4u : 2u;
            uint64_t bS1h = smem_desc(sb + FH_B0 + s1 * 16384);
            uint64_t bS1l = smem_desc(sb + FH_B0 + s1 * 16384 + 16384);
            uint64_t bS2h = smem_desc(sb + FH_B0 + s2 * 16384);
            uint64_t bS2l = smem_desc(sb + FH_B0 + s2 * 16384 + 16384);
#pragma unroll
            for (int ks = 0; ks < 4; ks++) {
                uint64_t o = (uint64_t)ks * 2;
                uint32_t e = (c == 0 && ks == 0) ? 0u : 1u;
                mma_f16_ss(tmem, aRh + o, bCh + o, IDESC_BF16, e);
                mma_f16_ss(tmem, aRh + o, bCl + o, IDESC_BF16, 1);
                mma_f16_ss(tmem, aRl + o, bCh + o, IDESC_BF16, 1);
                mma_f16_ss(tmem, aIh + o, bS1h + o, IDESC_BF16, 1);
                mma_f16_ss(tmem, aIh + o, bS1l + o, IDESC_BF16, 1);
                mma_f16_ss(tmem, aIl + o, bS1h + o, IDESC_BF16, 1);
                mma_f16_ss(tmem + 128, aIh + o, bCh + o, IDESC_BF16, e);
                mma_f16_ss(tmem + 128, aIh + o, bCl + o, IDESC_BF16, 1);
                mma_f16_ss(tmem + 128, aIl + o, bCh + o, IDESC_BF16, 1);
                mma_f16_ss(tmem + 128, aRh + o, bS2h + o, IDESC_BF16, 1);
                mma_f16_ss(tmem + 128, aRh + o, bS2l + o, IDESC_BF16, 1);
                mma_f16_ss(tmem + 128, aRl + o, bS2h + o, IDESC_BF16, 1);
            }
            TC_COMMIT(sb + 8);
        }
        MBAR_WAIT(sb + 8, c & 1);
        __syncthreads();
    }
    TC_FENCE_AFTER();
    int half = wid >> 2;
    int dloc = (wid & 3) * 32 + lane;
    uint32_t cb = tmem + half * 128;
    float* O = half ? Oi : Or;
    size_t base = outBase + d0 + dloc;
#pragma unroll
    for (int i = 0; i < 4; i++) {
        uint32_t r[32];
        TC_LD_X32(r, cb + 32 * i);
        TC_WAIT_LD();
#pragma unroll
        for (int j = 0; j < 32; j++)
            O[base + (size_t)(32 * i + j) * outStride] = __uint_as_float(r[j]);
    }
    __syncthreads();
    if (wid == 0) TC_DEALLOC(tmem, 256);
#endif
}

// -------------------- tensorized block-diagonal complex mixing ---------------
// Per (l, m-tile): Cr[m,n] = Xr·Wr − Xi·Wi, Ci[m,n] = Xr·Wi + Xi·Wr, N=96,
// K=96 padded to 128. A = X rows (k contiguous!), B = W^T tiles (with −Wi).
// LAYER 1: relu; LAYER 2: relu + softshrink.
#define MX_A0   1024
#define MX_B0   (1024 + 4 * 16384)     // A: Xr_h, Xr_l, Xi_h, Xi_l
#define MX_SMEM (MX_B0 + 6 * 12288)    // B: Wr_h,l  WiM_h,l  WiP_h,l -> 139264
template <int LAYER>
__global__ void __launch_bounds__(256, 1) k_mix_tc(const float* __restrict__ w,
                                                   const float* __restrict__ bias) {
#if TC_OK
    extern __shared__ char smem[];
    uint32_t sb = smem_u32(smem);
    int tid = threadIdx.x, wid = tid >> 5, lane = tid & 31;
    int l = blockIdx.x;
    int m0 = blockIdx.y * 128;
    const float* Xr = (LAYER == 1) ? g_Zr : g_Ar;
    const float* Xi = (LAYER == 1) ? g_Zi : g_Ai;
    float* Or = (LAYER == 1) ? g_Ar : g_Zr;
    float* Oi = (LAYER == 1) ? g_Ai : g_Zi;
    const float* wr = w + (size_t)l * BSv * BSv;
    const float* wi = w + (size_t)(NBv + l) * BSv * BSv;

    if (wid == 0) TC_ALLOC(sb, 256);
    if (tid == 0) MBAR_INIT(sb + 8, 1);
    __syncthreads();
    uint32_t tmem;
    asm volatile("ld.shared.b32 %0, [%1];" : "=r"(tmem) : "r"(sb));

    for (int c = 0; c < 2; c++) {
        int k0 = c * 64;
        // A: X rows [128 m][64 k] bf16 hi/lo, zero pad k>=96
        for (int idx = tid; idx < 4096; idx += 256) {
            int m = idx >> 5, kp = idx & 31;
            int k = kp * 2;
            size_t g = (size_t)(m0 + m) * Ddim + l * BSv + k0 + k;
            float r0 = (k0 + k     < BSv) ? Xr[g]     : 0.f;
            float r1 = (k0 + k + 1 < BSv) ? Xr[g + 1] : 0.f;
            float i0 = (k0 + k     < BSv) ? Xi[g]     : 0.f;
            float i1 = (k0 + k + 1 < BSv) ? Xi[g + 1] : 0.f;
            uint32_t sw = SWZ((uint32_t)(m * 128 + k * 2));
            *(uint32_t*)(smem + MX_A0 + sw)         = pack2(r0, r1, 0);
            *(uint32_t*)(smem + MX_A0 + 16384 + sw) = pack2(r0, r1, 1);
            *(uint32_t*)(smem + MX_A0 + 32768 + sw) = pack2(i0, i1, 0);
            *(uint32_t*)(smem + MX_A0 + 49152 + sw) = pack2(i0, i1, 1);
        }
        // B: W^T tiles [96 n][64 k] bf16: Wr, -Wi (for Cr), +Wi (for Ci)
        for (int idx = tid; idx < 3072; idx += 256) {
            int kp = idx / 96, n = idx % 96;
            int k = kp * 2;
            int gk0 = k0 + k, gk1 = k0 + k + 1;
            float wr0 = (gk0 < BSv) ? wr[gk0 * BSv + n] : 0.f;
            float wr1 = (gk1 < BSv) ? wr[gk1 * BSv + n] : 0.f;
            float wi0 = (gk0 < BSv) ? wi[gk0 * BSv + n] : 0.f;
            float wi1 = (gk1 < BSv) ? wi[gk1 * BSv + n] : 0.f;
            uint32_t sw = SWZ((uint32_t)(n * 128 + k * 2));
            *(uint32_t*)(smem + MX_B0 + sw)          = pack2(wr0, wr1, 0);
            *(uint32_t*)(smem + MX_B0 + 12288 + sw)  = pack2(wr0, wr1, 1);
            *(uint32_t*)(smem + MX_B0 + 24576 + sw)  = pack2(-wi0, -wi1, 0);
            *(uint32_t*)(smem + MX_B0 + 36864 + sw)  = pack2(-wi0, -wi1, 1);
            *(uint32_t*)(smem + MX_B0 + 49152 + sw)  = pack2(wi0, wi1, 0);
            *(uint32_t*)(smem + MX_B0 + 61440 + sw)  = pack2(wi0, wi1, 1);
        }
        FENCE_ASYNC();
        __syncthreads();
        if (tid == 0) {
            uint64_t aRh = smem_desc(sb + MX_A0),         aRl = smem_desc(sb + MX_A0 + 16384);
            uint64_t aIh = smem_desc(sb + MX_A0 + 32768), aIl = smem_desc(sb + MX_A0 + 49152);
            uint64_t bRh = smem_desc(sb + MX_B0),          bRl = smem_desc(sb + MX_B0 + 12288);
            uint64_t bMh = smem_desc(sb + MX_B0 + 24576),  bMl = smem_desc(sb + MX_B0 + 36864);
            uint64_t bPh = smem_desc(sb + MX_B0 + 49152),  bPl = smem_desc(sb + MX_B0 + 61440);
#pragma unroll
            for (int ks = 0; ks < 4; ks++) {
                uint64_t o = (uint64_t)ks * 2;
                uint32_t e = (c == 0 && ks == 0) ? 0u : 1u;
                // Cr (cols 0-95): Xr*Wr + Xi*(-Wi)
                mma_f16_ss(tmem, aRh + o, bRh + o, IDESC_N96, e);
                mma_f16_ss(tmem, aRh + o, bRl + o, IDESC_N96, 1);
                mma_f16_ss(tmem, aRl + o, bRh + o, IDESC_N96, 1);
                mma_f16_ss(tmem, aIh + o, bMh + o, IDESC_N96, 1);
                mma_f16_ss(tmem, aIh + o, bMl + o, IDESC_N96, 1);
                mma_f16_ss(tmem, aIl + o, bMh + o, IDESC_N96, 1);
                // Ci (cols 96-191): Xr*Wi + Xi*Wr
                mma_f16_ss(tmem + 96, aRh + o, bPh + o, IDESC_N96, e);
                mma_f16_ss(tmem + 96, aRh + o, bPl + o, IDESC_N96, 1);
                mma_f16_ss(tmem + 96, aRl + o, bPh + o, IDESC_N96, 1);
                mma_f16_ss(tmem + 96, aIh + o, bRh + o, IDESC_N96, 1);
                mma_f16_ss(tmem + 96, aIh + o, bRl + o, IDESC_N96, 1);
                mma_f16_ss(tmem + 96, aIl + o, bRh + o, IDESC_N96, 1);
            }
            TC_COMMIT(sb + 8);
        }
        MBAR_WAIT(sb + 8, c & 1);
        __syncthreads();
    }
    TC_FENCE_AFTER();
    // epilogue: bias + relu (+ softshrink), smem stage, coalesced store
    int half = wid >> 2;                   // 0 -> Cr, 1 -> Ci
    int mloc = (wid & 3) * 32 + lane;
    uint32_t cb = tmem + half * 96;
    const float* bh = bias + (half ? NBv * BSv : 0) + l * BSv;
    float* stage = (float*)(smem + 1024) + (size_t)half * 128 * 97;
#pragma unroll
    for (int i = 0; i < 3; i++) {
        uint32_t r[32];
        TC_LD_X32(r, cb + 32 * i);
        TC_WAIT_LD();
#pragma unroll
        for (int j = 0; j < 32; j++) {
            int n = 32 * i + j;
            float v = fmaxf(__uint_as_float(r[j]) + bh[n], 0.f);
            if (LAYER == 2) v = fmaxf(v - LAMv, 0.f);
            stage[mloc * 97 + n] = v;
        }
    }
    __syncthreads();
    float* sCr = (float*)(smem + 1024);
    float* sCi = sCr + 128 * 97;
    for (int idx = tid; idx < 128 * 96; idx += 256) {
        int row = idx / 96, n = idx % 96;
        size_t o = (size_t)(m0 + row) * Ddim + l * BSv + n;
        Or[o] = sCr[row * 97 + n];
        Oi[o] = sCi[row * 97 + n];
    }
    __syncthreads();
    if (wid == 0) TC_DEALLOC(tmem, 256);
#endif
}

// -------------------- tensorized irfft along W (transposed GEMM) -------------
#define FW_A0   1024
#define FW_B0   (1024 + 4 * 16384)
#define FW_SMEM (FW_B0 + 4 * 32768)
__global__ void __launch_bounds__(256, 1) k_ifftW_tc() {
#if TC_OK
    extern __shared__ char smem[];
    uint32_t sb = smem_u32(smem);
    int tid = threadIdx.x, wid = tid >> 5, lane = tid & 31;
    int z = blockIdx.y; int b = z >> 7; int h = z & 127;
    int d0 = blockIdx.x * 128;
    size_t slab = (size_t)(b * Hdim + h) * WFdim * Ddim;
    const float* Vr = g_Ar + slab;
    const float* Vi = g_Ai + slab;

    if (wid == 0) TC_ALLOC(sb, 256);
    if (tid == 0) MBAR_INIT(sb + 8, 1);
    __syncthreads();
    uint32_t tmem;
    asm volatile("ld.shared.b32 %0, [%1];" : "=r"(tmem) : "r"(sb));

    const __nv_bfloat16* gsrc[4] = {tCr_h, tCr_l, tCi_h, tCi_l};

    for (int c = 0; c < 3; c++) {
        int k0 = c * 64;
        for (int idx = tid; idx < 4096; idx += 256) {
            int kp = idx >> 7, d = idx & 127;
            int k = kp * 2;
            int g1 = k0 + k, g2 = k0 + k + 1;
            size_t ga = (size_t)g1 * Ddim + d0 + d;
            float r0 = (g1 < WFdim) ? Vr[ga] : 0.f;
            float i0 = (g1 < WFdim) ? Vi[ga] : 0.f;
            float r1 = (g2 < WFdim) ? Vr[ga + Ddim] : 0.f;
            float i1 = (g2 < WFdim) ? Vi[ga + Ddim] : 0.f;
            uint32_t sw = SWZ((uint32_t)(d * 128 + k * 2));
            *(uint32_t*)(smem + FW_A0 + sw)         = pack2(r0, r1, 0);
            *(uint32_t*)(smem + FW_A0 + 16384 + sw) = pack2(r0, r1, 1);
            *(uint32_t*)(smem + FW_A0 + 32768 + sw) = pack2(i0, i1, 0);
            *(uint32_t*)(smem + FW_A0 + 49152 + sw) = pack2(i0, i1, 1);
        }
        for (int idx = tid; idx < 8192; idx += 256) {
            int t = idx >> 11, r = idx & 2047, m = r >> 3, u = r & 7;
            uint4 v = *(const uint4*)(gsrc[t] + m * CKP + k0 + u * 8);
            *(uint4*)(smem + FW_B0 + t * 32768 + SWZ((uint32_t)(m * 128 + u * 16))) = v;
        }
        FENCE_ASYNC();
        __syncthreads();
        if (tid == 0) {
            uint64_t aRh = smem_desc(sb + FW_A0),         aRl = smem_desc(sb + FW_A0 + 16384);
            uint64_t aIh = smem_desc(sb + FW_A0 + 32768), aIl = smem_desc(sb + FW_A0 + 49152);
            uint64_t bRh = smem_desc(sb + FW_B0),          bRl = smem_desc(sb + FW_B0 + 32768);
            uint64_t bIh = smem_desc(sb + FW_B0 + 65536),  bIl = smem_desc(sb + FW_B0 + 98304);
#pragma unroll
            for (int ks = 0; ks < 4; ks++) {
                uint64_t o = (uint64_t)ks * 2;
                uint32_t e = (c == 0 && ks == 0) ? 0u : 1u;
                mma_f16_ss(tmem, aRh + o, bRh + o, IDESC_N256, e);
                mma_f16_ss(tmem, aRh + o, bRl + o, IDESC_N256, 1);
                mma_f16_ss(tmem, aRl + o, bRh + o, IDESC_N256, 1);
                mma_f16_ss(tmem, aIh + o, bIh + o, IDESC_N256, 1);
                mma_f16_ss(tmem, aIh + o, bIl + o, IDESC_N256, 1);
                mma_f16_ss(tmem, aIl + o, bIh + o, IDESC_N256, 1);
            }
            TC_COMMIT(sb + 8);
        }
        MBAR_WAIT(sb + 8, c & 1);
        __syncthreads();
    }
    TC_FENCE_AFTER();
    int half = wid >> 2;
    int dloc = (wid & 3) * 32 + lane;
    uint32_t cb = tmem + half * 128;
    size_t rowBase = (size_t)(b * 32768 + h * 256 + half * 128) * Ddim + d0 + dloc;
#pragma unroll
    for (int i = 0; i < 4; i++) {
        uint32_t r[32];
        TC_LD_X32(r, cb + 32 * i);
        TC_WAIT_LD();
#pragma unroll
        for (int j = 0; j < 32; j++)
            g_P[rowBase + (size_t)(32 * i + j) * Ddim] = __uint_as_float(r[j]);
    }
    __syncthreads();
    if (wid == 0) TC_DEALLOC(tmem, 256);
#endif
}

// -------------------- tcgen05 MLP GEMM: 256x128 tile, staged epilogue --------
#define GT_STAGES 2
#define GT_A_BYTES 32768
#define GT_B_BYTES 16384
#define GT_STAGE_BYTES (2 * GT_A_BYTES + 2 * GT_B_BYTES)
#define GT_SMEM (1024 + GT_STAGES * GT_STAGE_BYTES)

template <int EPI>
__global__ void __launch_bounds__(256, 1)
k_gemm_tc(const __grid_constant__ CUtensorMap tAh, const __grid_constant__ CUtensorMap tAl,
          const __grid_constant__ CUtensorMap tBh, const __grid_constant__ CUtensorMap tBl,
          const float* __restrict__ bias, const float* __restrict__ resid,
          float* __restrict__ outF, __nv_bfloat16* __restrict__ outHi,
          __nv_bfloat16* __restrict__ outLo, int K, int N) {
#if TC_OK
    extern __shared__ char smem[];
    uint32_t sb = smem_u32(smem);
    int tid = threadIdx.x, wid = tid >> 5, lane = tid & 31;
    int m0 = blockIdx.y * 256, n0 = blockIdx.x * 128;
    int nChunks = K >> 6;

    if (wid == 0) TC_ALLOC(sb, 256);
    if (tid == 0) {
#pragma unroll
        for (int s = 0; s < GT_STAGES; s++) { MBAR_INIT(sb + 16 + 8 * s, 1); MBAR_INIT(sb + 48 + 8 * s, 1); }
        MBAR_INIT(sb + 80, 1);
    }
    __syncthreads();
    uint32_t tmem;
    asm volatile("ld.shared.b32 %0, [%1];" : "=r"(tmem) : "r"(sb));

    if (tid == 0) {
        int s = 0, ph = 1;
        for (int c = 0; c < nChunks; c++) {
            MBAR_WAIT_RELAXED(sb + 48 + 8 * s, ph);
            MBAR_EXPECT_TX(sb + 16 + 8 * s, GT_STAGE_BYTES);
            uint32_t t0 = sb + 1024 + s * GT_STAGE_BYTES;
            TMA_LOAD_2D(t0,                               &tAh, c * 64, m0, sb + 16 + 8 * s);
            TMA_LOAD_2D(t0 + GT_A_BYTES,                  &tAl, c * 64, m0, sb + 16 + 8 * s);
            TMA_LOAD_2D(t0 + 2 * GT_A_BYTES,              &tBh, c * 64, n0, sb + 16 + 8 * s);
            TMA_LOAD_2D(t0 + 2 * GT_A_BYTES + GT_B_BYTES, &tBl, c * 64, n0, sb + 16 + 8 * s);
            if (++s == GT_STAGES) { s = 0; ph ^= 1; }
        }
    }
    if (tid == 32) {
        int s = 0, ph = 0;
        for (int c = 0; c < nChunks; c++) {
            MBAR_WAIT(sb + 16 + 8 * s, ph);
            uint32_t t0 = sb + 1024 + s * GT_STAGE_BYTES;
            uint64_t dBh = smem_desc(t0 + 2 * GT_A_BYTES);
            uint64_t dBl = smem_desc(t0 + 2 * GT_A_BYTES + GT_B_BYTES);
#pragma unroll
            for (int mb = 0; mb < 2; mb++) {
                uint64_t dAh = smem_desc(t0 + mb * 16384);
                uint64_t dAl = smem_desc(t0 + GT_A_BYTES + mb * 16384);
                uint32_t dst = tmem + mb * 128;
#pragma unroll
                for (int ks = 0; ks < 4; ks++) {
                    uint32_t en = (c > 0 || ks > 0) ? 1u : 0u;
                    mma_f16_ss(dst, dAh + ks * 2, dBh + ks * 2, IDESC_BF16, en);
                    mma_f16_ss(dst, dAh + ks * 2, dBl + ks * 2, IDESC_BF16, 1);
                    mma_f16_ss(dst, dAl + ks * 2, dBh + ks * 2, IDESC_BF16, 1);
                }
            }
            TC_COMMIT(sb + 48 + 8 * s);
            if (++s == GT_STAGES) { s = 0; ph ^= 1; }
        }
        TC_COMMIT(sb + 80);
    }

    MBAR_WAIT(sb + 80, 0);
    TC_FENCE_AFTER();

    int mb = wid >> 2;
    int mloc = mb * 128 + (wid & 3) * 32 + lane;
    uint32_t cbase = tmem + mb * 128;

    if (EPI == 0) {
        __nv_bfloat16* sHi = (__nv_bfloat16*)(smem + 1024);
        __nv_bfloat16* sLo = sHi + 256 * 130;
#pragma unroll
        for (int i = 0; i < 4; i++) {
            uint32_t r[32];
            TC_LD_X32(r, cbase + 32 * i);
            TC_WAIT_LD();
#pragma unroll
            for (int j = 0; j < 32; j++) {
                int n = n0 + 32 * i + j;
                float v = __uint_as_float(r[j]) + bias[n];
                float g = 0.5f * v * (1.f + erff(v * 0.70710678118654752f));
                __nv_bfloat16 hi, lo;
                split2(g, &hi, &lo);
                sHi[mloc * 130 + 32 * i + j] = hi;
                sLo[mloc * 130 + 32 * i + j] = lo;
            }
        }
        __syncthreads();
        const uint32_t* sHi32 = (const uint32_t*)sHi;
        const uint32_t* sLo32 = (const uint32_t*)sLo;
        uint32_t* oHi32 = (uint32_t*)outHi;
        uint32_t* oLo32 = (uint32_t*)outLo;
        int halfN = N >> 1;
        for (int idx = tid; idx < 256 * 64; idx += 256) {
            int row = idx >> 6, c = idx & 63;
            size_t o = (size_t)(m0 + row) * halfN + (n0 >> 1) + c;
            oHi32[o] = sHi32[row * 65 + c];
            oLo32[o] = sLo32[row * 65 + c];
        }
    } else {
        float* sF = (float*)(smem + 1024);
#pragma unroll
        for (int i = 0; i < 4; i++) {
            uint32_t r[32];
            TC_LD_X32(r, cbase + 32 * i);
            TC_WAIT_LD();
#pragma unroll
            for (int j = 0; j < 32; j++)
                sF[mloc * 129 + 32 * i + j] = __uint_as_float(r[j]);
        }
        __syncthreads();
        for (int idx = tid; idx < 256 * 128; idx += 256) {
            int row = idx >> 7, c = idx & 127;
            size_t o = (size_t)(m0 + row) * N + n0 + c;
            outF[o] = sF[row * 129 + c] + bias[n0 + c] + resid[o];
        }
    }
    __syncthreads();
    if (wid == 0) TC_DEALLOC(tmem, 256);
#endif
}

// -------------------- host: tensor map construction --------------------------
typedef CUresult (*EncodeFn)(CUtensorMap*, CUtensorMapDataType, cuuint32_t, void*,
                             const cuuint64_t*, const cuuint64_t*, const cuuint32_t*,
                             const cuuint32_t*, CUtensorMapInterleave, CUtensorMapSwizzle,
                             CUtensorMapL2promotion, CUtensorMapFloatOOBfill);

static void makeMap(EncodeFn enc, CUtensorMap* m, void* ptr, uint64_t d0, uint64_t d1,
                    uint32_t boxRows) {
    cuuint64_t dims[2] = {d0, d1};
    cuuint64_t strides[1] = {d0 * 2};
    cuuint32_t box[2] = {64, boxRows};
    cuuint32_t es[2] = {1, 1};
    enc(m, CU_TENSOR_MAP_DATA_TYPE_BFLOAT16, 2, ptr, dims, strides, box, es,
        CU_TENSOR_MAP_INTERLEAVE_NONE, CU_TENSOR_MAP_SWIZZLE_128B,
        CU_TENSOR_MAP_L2_PROMOTION_L2_128B, CU_TENSOR_MAP_FLOAT_OOB_FILL_NONE);
}

// ---------------------------------------------------------------------------
extern "C" void kernel_launch(void* const* d_in, const int* in_sizes, int n_in,
                              void* d_out, int out_size) {
    const float* x    = (const float*)d_in[0];
    const float* n1g  = (const float*)d_in[1];
    const float* n1b  = (const float*)d_in[2];
    const float* w1   = (const float*)d_in[3];
    const float* w2   = (const float*)d_in[4];
    const float* b1   = (const float*)d_in[5];
    const float* b2   = (const float*)d_in[6];
    const float* n2g  = (const float*)d_in[7];
    const float* n2b  = (const float*)d_in[8];
    const float* fc1w = (const float*)d_in[9];
    const float* fc1b = (const float*)d_in[10];
    const float* fc2w = (const float*)d_in[11];
    const float* fc2b = (const float*)d_in[12];
    float* out = (float*)d_out;

    float *pT, *pP;
    cudaGetSymbolAddress((void**)&pT, g_T);
    cudaGetSymbolAddress((void**)&pP, g_P);
    void *pAh, *pAl, *pHh, *pHl, *pW1h, *pW1l, *pW2h, *pW2l;
    cudaGetSymbolAddress(&pAh, gA_hi);  cudaGetSymbolAddress(&pAl, gA_lo);
    cudaGetSymbolAddress(&pHh, gH_hi);  cudaGetSymbolAddress(&pHl, gH_lo);
    cudaGetSymbolAddress(&pW1h, gW1T_hi); cudaGetSymbolAddress(&pW1l, gW1T_lo);
    cudaGetSymbolAddress(&pW2h, gW2T_hi); cudaGetSymbolAddress(&pW2l, gW2T_lo);

    EncodeFn enc = nullptr;
    cudaDriverEntryPointQueryResult qr;
    cudaGetDriverEntryPoint("cuTensorMapEncodeTiled", (void**)&enc, cudaEnableDefault, &qr);

    CUtensorMap mAh, mAl, mW1h, mW1l, mHh, mHl, mW2h, mW2l;
    makeMap(enc, &mAh, pAh, Ddim, TOKENS, 256);
    makeMap(enc, &mAl, pAl, Ddim, TOKENS, 256);
    makeMap(enc, &mW1h, pW1h, Ddim, HIDv, 128);
    makeMap(enc, &mW1l, pW1l, Ddim, HIDv, 128);
    makeMap(enc, &mHh, pHh, HIDv, TOKENS, 256);
    makeMap(enc, &mHl, pHl, HIDv, TOKENS, 256);
    makeMap(enc, &mW2h, pW2h, HIDv, Ddim, 128);
    makeMap(enc, &mW2l, pW2l, HIDv, Ddim, 128);

    cudaFuncSetAttribute(k_gemm_tc<0>, cudaFuncAttributeMaxDynamicSharedMemorySize, GT_SMEM);
    cudaFuncSetAttribute(k_gemm_tc<1>, cudaFuncAttributeMaxDynamicSharedMemorySize, GT_SMEM);
    cudaFuncSetAttribute(k_fftH_tc<0>, cudaFuncAttributeMaxDynamicSharedMemorySize, FH_SMEM);
    cudaFuncSetAttribute(k_fftH_tc<1>, cudaFuncAttributeMaxDynamicSharedMemorySize, FH_SMEM);
    cudaFuncSetAttribute(k_ifftW_tc, cudaFuncAttributeMaxDynamicSharedMemorySize, FW_SMEM);
    cudaFuncSetAttribute(k_mix_tc<1>, cudaFuncAttributeMaxDynamicSharedMemorySize, MX_SMEM);
    cudaFuncSetAttribute(k_mix_tc<2>, cudaFuncAttributeMaxDynamicSharedMemorySize, MX_SMEM);

    k_init<<<192, 256>>>();
    k_ln<0><<<TOKENS, 256>>>(x, n1g, n1b, pT, nullptr, nullptr);
    k_fftW<<<dim3(12, 1, 256), 256>>>(pT);
    k_fftH_tc<0><<<dim3(6, 258), 256, FH_SMEM>>>();
    k_mix_tc<1><<<dim3(8, 258), 256, MX_SMEM>>>(w1, b1);
    k_mix_tc<2><<<dim3(8, 258), 256, MX_SMEM>>>(w2, b2);
    k_fftH_tc<1><<<dim3(6, 258), 256, FH_SMEM>>>();
    k_ifftW_tc<<<dim3(6, 256), 256, FW_SMEM>>>();
    k_ln<1><<<TOKENS, 256>>>(pP, n2g, n2b, nullptr,
                             (__nv_bfloat16*)pAh, (__nv_bfloat16*)pAl);
    dim3 tb(32, 8);
    k_splitT<<<dim3(HIDv / 32, Ddim / 32), tb>>>(fc1w, (__nv_bfloat16*)pW1h,
                                                 (__nv_bfloat16*)pW1l, Ddim, HIDv);
    k_splitT<<<dim3(Ddim / 32, HIDv / 32), tb>>>(fc2w, (__nv_bfloat16*)pW2h,
                                                 (__nv_bfloat16*)pW2l, HIDv, Ddim);
    k_gemm_tc<0><<<dim3(HIDv / 128, TOKENS / 256), 256, GT_SMEM>>>(
        mAh, mAl, mW1h, mW1l, fc1b, nullptr, nullptr,
        (__nv_bfloat16*)pHh, (__nv_bfloat16*)pHl, Ddim, HIDv);
    k_gemm_tc<1><<<dim3(Ddim / 128, TOKENS / 256), 256, GT_SMEM>>>(
        mHh, mHl, mW2h, mW2l, fc2b, x, out, nullptr, nullptr, HIDv, Ddim);
}

// round 14
// speedup vs baseline: 1.1183x; 1.1183x over previous
#include <cuda_runtime.h>
#include <cuda_bf16.h>
#include <cuda.h>
#include <math.h>
#include <stdint.h>

// ---------------------------------------------------------------------------
// AFNO block. LN/fftW/mix SIMT fp32 (fftW computes the Nyquist row inline).
// fftH (fwd+inv) + ifftW on tcgen05 bf16 hi/lo (3-term) via transposed-GEMM
// K-major SS path. MLP on tcgen05 bf16 hi/lo, M=256 tiles, staged epilogue.
// ---------------------------------------------------------------------------

#if defined(__CUDA_ARCH__) && (defined(__CUDA_ARCH_FEAT_SM103_ALL) || \
    defined(__CUDA_ARCH_FEAT_SM100_ALL) || defined(__CUDA_ARCH_FEAT_SM101_ALL))
#define TC_OK 1
#else
#define TC_OK 0
#endif

#define Hdim   128
#define Wdim   256
#define WFdim  129
#define Ddim   768
#define NBv    8
#define BSv    96
#define HIDv   3072
#define TOKENS 65536
#define NPOSv  33024
#define LAMv   0.01f
#define CKP    192

// -------------------- scratch (device globals; no allocation) ---------------
__device__ float g_P [(size_t)TOKENS * Ddim];
__device__ float g_T [(size_t)TOKENS * Ddim];
__device__ float g_Yr[(size_t)NPOSv * Ddim];
__device__ float g_Yi[(size_t)NPOSv * Ddim];
__device__ float g_Zr[(size_t)NPOSv * Ddim];
__device__ float g_Zi[(size_t)NPOSv * Ddim];
__device__ float g_Ar[(size_t)NPOSv * Ddim];
__device__ float g_Ai[(size_t)NPOSv * Ddim];
// bf16 hi/lo operands for tensor-core MLP
__device__ __align__(1024) __nv_bfloat16 gA_hi[(size_t)TOKENS * Ddim];
__device__ __align__(1024) __nv_bfloat16 gA_lo[(size_t)TOKENS * Ddim];
__device__ __align__(1024) __nv_bfloat16 gH_hi[(size_t)TOKENS * HIDv];
__device__ __align__(1024) __nv_bfloat16 gH_lo[(size_t)TOKENS * HIDv];
__device__ __align__(1024) __nv_bfloat16 gW1T_hi[(size_t)HIDv * Ddim];
__device__ __align__(1024) __nv_bfloat16 gW1T_lo[(size_t)HIDv * Ddim];
__device__ __align__(1024) __nv_bfloat16 gW2T_hi[(size_t)Ddim * HIDv];
__device__ __align__(1024) __nv_bfloat16 gW2T_lo[(size_t)Ddim * HIDv];
// DFT tables
__device__ float g_FcT[Wdim * WFdim], g_FsT[Wdim * WFdim];   // fp32 [w][wf] (fftW SIMT)
__device__ __align__(16) __nv_bfloat16 tGc_h [Hdim * Hdim], tGc_l [Hdim * Hdim];
__device__ __align__(16) __nv_bfloat16 tGsP_h[Hdim * Hdim], tGsP_l[Hdim * Hdim];
__device__ __align__(16) __nv_bfloat16 tGsM_h[Hdim * Hdim], tGsM_l[Hdim * Hdim];
__device__ __align__(16) __nv_bfloat16 tCr_h [Wdim * CKP],  tCr_l [Wdim * CKP];
__device__ __align__(16) __nv_bfloat16 tCi_h [Wdim * CKP],  tCi_l [Wdim * CKP];

// -------------------- PTX helpers -------------------------------------------
__device__ __forceinline__ uint32_t smem_u32(const void* p) {
    uint32_t a;
    asm("{ .reg .u64 t; cvta.to.shared.u64 t, %1; cvt.u32.u64 %0, t; }" : "=r"(a) : "l"(p));
    return a;
}
#define MBAR_INIT(a, c) \
    asm volatile("mbarrier.init.shared.b64 [%0], %1;" :: "r"(a), "r"(c) : "memory")
#define MBAR_EXPECT_TX(a, b) \
    asm volatile("mbarrier.arrive.expect_tx.shared.b64 _, [%0], %1;" :: "r"(a), "r"(b) : "memory")
#define MBAR_WAIT(a, ph) do { \
    uint32_t _m = (a), _p = (ph), _d; \
    asm volatile("{\n\t.reg .pred p;\n\t" \
        "mbarrier.try_wait.parity.acquire.cta.shared::cta.b64 p, [%1], %2;\n\t" \
        "selp.b32 %0, 1, 0, p;\n\t}" : "=r"(_d) : "r"(_m), "r"(_p) : "memory"); \
    if (!_d) { asm volatile("{\n\t.reg .pred P1;\n\tWL%=:\n\t" \
        "mbarrier.try_wait.parity.acquire.cta.shared::cta.b64 P1, [%0], %1, 0x989680;\n\t" \
        "@P1 bra.uni WD%=;\n\tbra.uni WL%=;\n\tWD%=:\n\t}" :: "r"(_m), "r"(_p) : "memory"); } \
} while(0)
#define MBAR_WAIT_RELAXED(a, ph) do { \
    uint32_t _m = (a), _p = (ph), _d; \
    asm volatile("{\n\t.reg .pred p;\n\t" \
        "mbarrier.try_wait.parity.relaxed.cta.shared::cta.b64 p, [%1], %2, 0x989680;\n\t" \
        "selp.b32 %0, 1, 0, p;\n\t}" : "=r"(_d) : "r"(_m), "r"(_p) : "memory"); \
    if (!_d) { asm volatile("{\n\t.reg .pred P1;\n\tWL%=:\n\t" \
        "mbarrier.try_wait.parity.relaxed.cta.shared::cta.b64 P1, [%0], %1, 0x989680;\n\t" \
        "@P1 bra.uni WD%=;\n\tbra.uni WL%=;\n\tWD%=:\n\t}" :: "r"(_m), "r"(_p) : "memory"); } \
} while(0)
#define TMA_LOAD_2D(dst, map, cx, cy, mbar) \
    asm volatile("cp.async.bulk.tensor.2d.shared::cta.global.tile.mbarrier::complete_tx::bytes " \
        "[%0], [%1, {%2, %3}], [%4];" \
        :: "r"(dst), "l"(map), "r"(cx), "r"(cy), "r"(mbar) : "memory")
#define TC_ALLOC(sm, n) \
    asm volatile("tcgen05.alloc.cta_group::1.sync.aligned.shared::cta.b32 [%0], %1;" \
        :: "r"(sm), "r"(n) : "memory")
#define TC_DEALLOC(t, n) \
    asm volatile("tcgen05.dealloc.cta_group::1.sync.aligned.b32 %0, %1;" :: "r"(t), "r"(n))
#define TC_COMMIT(mbar) \
    asm volatile("tcgen05.commit.cta_group::1.mbarrier::arrive::one.shared::cluster.b64 [%0];" \
        :: "r"(mbar) : "memory")
#define TC_FENCE_AFTER() asm volatile("tcgen05.fence::after_thread_sync;" ::: "memory")
#define TC_WAIT_LD() asm volatile("tcgen05.wait::ld.sync.aligned;" ::: "memory")
#define FENCE_ASYNC() asm volatile("fence.proxy.async.shared::cta;" ::: "memory")
#define TC_LD_X32(r, addr) \
    asm volatile("tcgen05.ld.sync.aligned.32x32b.x32.b32 " \
        "{%0,%1,%2,%3,%4,%5,%6,%7,%8,%9,%10,%11,%12,%13,%14,%15," \
        "%16,%17,%18,%19,%20,%21,%22,%23,%24,%25,%26,%27,%28,%29,%30,%31}, [%32];" \
        : "=r"((r)[0]),"=r"((r)[1]),"=r"((r)[2]),"=r"((r)[3]),"=r"((r)[4]),"=r"((r)[5]), \
          "=r"((r)[6]),"=r"((r)[7]),"=r"((r)[8]),"=r"((r)[9]),"=r"((r)[10]),"=r"((r)[11]), \
          "=r"((r)[12]),"=r"((r)[13]),"=r"((r)[14]),"=r"((r)[15]),"=r"((r)[16]),"=r"((r)[17]), \
          "=r"((r)[18]),"=r"((r)[19]),"=r"((r)[20]),"=r"((r)[21]),"=r"((r)[22]),"=r"((r)[23]), \
          "=r"((r)[24]),"=r"((r)[25]),"=r"((r)[26]),"=r"((r)[27]),"=r"((r)[28]),"=r"((r)[29]), \
          "=r"((r)[30]),"=r"((r)[31]) : "r"(addr))

__device__ __forceinline__ void mma_f16_ss(uint32_t d, uint64_t ad, uint64_t bd,
                                           uint32_t idesc, uint32_t en) {
#if TC_OK
    asm volatile("{\n\t.reg .pred p;\n\tsetp.ne.u32 p, %4, 0;\n\t"
        "tcgen05.mma.cta_group::1.kind::f16 [%0], %1, %2, %3, {%5, %5, %5, %5}, p;\n\t}"
        :: "r"(d), "l"(ad), "l"(bd), "r"(idesc), "r"(en), "r"(0u) : "memory");
#endif
}
// K-major SW128 desc (LBO=1, SBO=64) — the proven layout
__device__ __forceinline__ uint64_t smem_desc(uint32_t addr) {
    return ((uint64_t)2 << 61) | ((uint64_t)1 << 46) | ((uint64_t)64 << 32)
         | ((uint64_t)1 << 16) | (uint64_t)((addr >> 4) & 0x3FFF);
}
__device__ __forceinline__ void split2(float v, __nv_bfloat16* h, __nv_bfloat16* l) {
    *h = __float2bfloat16_rn(v);
    *l = __float2bfloat16_rn(v - __bfloat162float(*h));
}
__device__ __forceinline__ uint32_t pack2(float v0, float v1, int lo) {
    __nv_bfloat16 h0, l0, h1, l1;
    split2(v0, &h0, &l0); split2(v1, &h1, &l1);
    __nv_bfloat16 a = lo ? l0 : h0, b = lo ? l1 : h1;
    return (uint32_t)__bfloat16_as_ushort(a) | ((uint32_t)__bfloat16_as_ushort(b) << 16);
}
#define SWZ(x) ((x) ^ (((x) >> 3) & 0x70))

#define IDESC_BF16 ((1u << 4) | (1u << 7) | (1u << 10) | (16u << 17) | (8u << 24))
#define IDESC_N256 ((1u << 4) | (1u << 7) | (1u << 10) | (32u << 17) | (8u << 24))

// -------------------- DFT table init ----------------------------------------
__global__ void k_init() {
    int i = blockIdx.x * 256 + threadIdx.x;
    const double PI2 = 6.283185307179586476925286766559;
    const double S = sqrt(32768.0);
    if (i < Wdim * WFdim) {
        int w = i / WFdim, wf = i % WFdim;
        double th = PI2 * (double)((wf * w) % Wdim) / (double)Wdim;
        g_FcT[i] = (float)( cos(th) / S);
        g_FsT[i] = (float)(-sin(th) / S);
    }
    if (i < Hdim * Hdim) {
        int m = i >> 7, k = i & 127;
        double ph = PI2 * (double)((m * k) % Hdim) / (double)Hdim;
        float cv = (float)cos(ph), sv = (float)sin(ph);
        split2(cv,  &tGc_h[i],  &tGc_l[i]);
        split2(sv,  &tGsP_h[i], &tGsP_l[i]);
        split2(-sv, &tGsM_h[i], &tGsM_l[i]);
    }
    if (i < Wdim * CKP) {
        int w = i / CKP, wf = i % CKP;
        float cr = 0.f, ci = 0.f;
        if (wf < WFdim) {
            double th = PI2 * (double)((wf * w) % Wdim) / (double)Wdim;
            double a = (wf == 0 || wf == Wdim / 2) ? 1.0 : 2.0;
            cr = (float)( a * cos(th) / S);
            ci = (float)(-a * sin(th) / S);
        }
        split2(cr, &tCr_h[i], &tCr_l[i]);
        split2(ci, &tCi_h[i], &tCi_l[i]);
    }
}

// -------------------- LayerNorm (SPLIT=1: emit bf16 hi/lo) -------------------
template <int SPLIT>
__global__ void k_ln(const float* __restrict__ in, const float* __restrict__ gam,
                     const float* __restrict__ bet, float* __restrict__ out,
                     __nv_bfloat16* __restrict__ ohi, __nv_bfloat16* __restrict__ olo) {
    int t = blockIdx.x;
    const float* xp = in + (size_t)t * Ddim;
    int tid = threadIdx.x;
    float v[3], s = 0.f, s2 = 0.f;
#pragma unroll
    for (int i = 0; i < 3; i++) { v[i] = xp[tid + i * 256]; s += v[i]; s2 += v[i] * v[i]; }
#pragma unroll
    for (int o = 16; o; o >>= 1) {
        s  += __shfl_xor_sync(0xffffffffu, s,  o);
        s2 += __shfl_xor_sync(0xffffffffu, s2, o);
    }
    __shared__ float sh[2][8];
    __shared__ float mu_s, rs_s;
    int w = tid >> 5;
    if ((tid & 31) == 0) { sh[0][w] = s; sh[1][w] = s2; }
    __syncthreads();
    if (tid == 0) {
        float ts = 0.f, ts2 = 0.f;
#pragma unroll
        for (int i = 0; i < 8; i++) { ts += sh[0][i]; ts2 += sh[1][i]; }
        float mu = ts * (1.f / 768.f);
        float var = ts2 * (1.f / 768.f) - mu * mu;
        mu_s = mu; rs_s = rsqrtf(var + 1e-5f);
    }
    __syncthreads();
    float mu = mu_s, rs = rs_s;
#pragma unroll
    for (int i = 0; i < 3; i++) {
        int c = tid + i * 256;
        float r = (v[i] - mu) * rs * gam[c] + bet[c];
        if (SPLIT == 0) {
            out[(size_t)t * Ddim + c] = r;
        } else {
            __nv_bfloat16 hi, lo;
            split2(r, &hi, &lo);
            ohi[(size_t)t * Ddim + c] = hi;
            olo[(size_t)t * Ddim + c] = lo;
        }
    }
}

// -------------------- transpose + split weights ------------------------------
__global__ void k_splitT(const float* __restrict__ in, __nv_bfloat16* __restrict__ oh,
                         __nv_bfloat16* __restrict__ ol, int R, int C) {
    __shared__ float t[32][33];
    int c0 = blockIdx.x * 32, r0 = blockIdx.y * 32;
    int x = threadIdx.x, y = threadIdx.y;
#pragma unroll
    for (int i = 0; i < 32; i += 8)
        t[y + i][x] = in[(size_t)(r0 + y + i) * C + c0 + x];
    __syncthreads();
#pragma unroll
    for (int i = 0; i < 32; i += 8) {
        __nv_bfloat16 hi, lo;
        split2(t[x][y + i], &hi, &lo);
        size_t o = (size_t)(c0 + y + i) * R + r0 + x;
        oh[o] = hi; ol[o] = lo;
    }
}

// -------------------- rfft along W: wf 0..127 + inline Nyquist ---------------
__global__ void __launch_bounds__(256, 2) k_fftW(const float* __restrict__ X) {
    int bh = blockIdx.z; int b = bh >> 7; int h = bh & 127;
    int n0 = blockIdx.x * 64;
    const float* B = X + ((size_t)(b * 32768 + h * 256)) * Ddim;
    __shared__ float Ac[16][128], As[16][128], Bs[16][64];
    int tid = threadIdx.x, tx = tid & 15, ty = tid >> 4;
    float accr[8][4] = {}, acci[8][4] = {};
    float nyq = 0.f;
    for (int k0 = 0; k0 < Wdim; k0 += 16) {
#pragma unroll
        for (int i = 0; i < 8; i++) {
            int e = tid + i * 256; int k = e >> 7, m = e & 127;
            Ac[k][m] = g_FcT[(k0 + k) * WFdim + m];
            As[k][m] = g_FsT[(k0 + k) * WFdim + m];
        }
#pragma unroll
        for (int i = 0; i < 4; i++) {
            int e = tid + i * 256; int k = e >> 6, n = e & 63;
            float v = B[(size_t)(k0 + k) * Ddim + n0 + n];
            Bs[k][n] = v;
            nyq += ((k0 + k) & 1) ? -v : v;
        }
        __syncthreads();
#pragma unroll
        for (int kk = 0; kk < 16; kk++) {
            float a0[8], a1[8], bb[4];
#pragma unroll
            for (int i = 0; i < 8; i++) { a0[i] = Ac[kk][ty * 8 + i]; a1[i] = As[kk][ty * 8 + i]; }
#pragma unroll
            for (int j = 0; j < 4; j++) bb[j] = Bs[kk][tx * 4 + j];
#pragma unroll
            for (int i = 0; i < 8; i++)
#pragma unroll
                for (int j = 0; j < 4; j++) {
                    accr[i][j] += a0[i] * bb[j];
                    acci[i][j] += a1[i] * bb[j];
                }
        }
        __syncthreads();
    }
#pragma unroll
    for (int i = 0; i < 8; i++) {
        int gm = ty * 8 + i;
        size_t base = ((size_t)((b * WFdim + gm) * Hdim + h)) * Ddim + n0 + tx * 4;
#pragma unroll
        for (int j = 0; j < 4; j++) { g_Yr[base + j] = accr[i][j]; g_Yi[base + j] = acci[i][j]; }
    }
    // Nyquist row wf=128: per-thread partial holds 4 distinct n-columns
    // (n = tx*4..tx*4+3 pattern does NOT hold; each thread covered every
    // (k,n) with n == (tid + i*256) & 63 -> n = tid & 63). Reduce by n.
    float* red = &Ac[0][0];
    __syncthreads();
    red[tid] = nyq;
    __syncthreads();
    if (tid < 64) {
        float s = red[tid] + red[tid + 64] + red[tid + 128] + red[tid + 192];
        size_t base = ((size_t)((b * WFdim + 128) * Hdim + h)) * Ddim + n0 + tid;
        g_Yr[base] = s * (1.f / 181.01933598375617f);
        g_Yi[base] = 0.f;
    }
}

// -------------------- tensorized complex FFT along H (transposed GEMM) -------
#define FH_A0   1024
#define FH_B0   (1024 + 4 * 16384)
#define FH_SMEM (FH_B0 + 6 * 16384)
template <int INV>
__global__ void __launch_bounds__(256, 1) k_fftH_tc() {
#if TC_OK
    extern __shared__ char smem[];
    uint32_t sb = smem_u32(smem);
    int tid = threadIdx.x, wid = tid >> 5, lane = tid & 31;
    int z = blockIdx.y; int b = z / WFdim; int wf = z % WFdim;
    int d0 = blockIdx.x * 128;
    size_t slab = (size_t)(b * WFdim + wf) * Hdim * Ddim;
    const float* Br = (INV == 0) ? (g_Yr + slab) : (g_Zr + slab);
    const float* Bi = (INV == 0) ? (g_Yi + slab) : (g_Zi + slab);
    float* Or = (INV == 0) ? g_Zr : g_Ar;
    float* Oi = (INV == 0) ? g_Zi : g_Ai;
    size_t outBase = (INV == 0) ? slab : ((size_t)b * Hdim * WFdim + wf) * Ddim;
    size_t outStride = (INV == 0) ? (size_t)Ddim : (size_t)WFdim * Ddim;

    if (wid == 0) TC_ALLOC(sb, 256);
    if (tid == 0) MBAR_INIT(sb + 8, 1);
    __syncthreads();
    uint32_t tmem;
    asm volatile("ld.shared.b32 %0, [%1];" : "=r"(tmem) : "r"(sb));

    const __nv_bfloat16* gsrc[6] = {tGc_h, tGc_l, tGsP_h, tGsP_l, tGsM_h, tGsM_l};

    for (int c = 0; c < 2; c++) {
        int k0 = c * 64;
        for (int idx = tid; idx < 4096; idx += 256) {
            int hp = idx >> 7, d = idx & 127;
            int h = hp * 2;
            size_t g0 = (size_t)(k0 + h) * Ddim + d0 + d;
            float r0 = Br[g0], r1 = Br[g0 + Ddim];
            float i0 = Bi[g0], i1 = Bi[g0 + Ddim];
            uint32_t sw = SWZ((uint32_t)(d * 128 + h * 2));
            *(uint32_t*)(smem + FH_A0 + sw)         = pack2(r0, r1, 0);
            *(uint32_t*)(smem + FH_A0 + 16384 + sw) = pack2(r0, r1, 1);
            *(uint32_t*)(smem + FH_A0 + 32768 + sw) = pack2(i0, i1, 0);
            *(uint32_t*)(smem + FH_A0 + 49152 + sw) = pack2(i0, i1, 1);
        }
        for (int idx = tid; idx < 6144; idx += 256) {
            int t = idx >> 10, r = idx & 1023, m = r >> 3, u = r & 7;
            uint4 v = *(const uint4*)(gsrc[t] + m * Hdim + k0 + u * 8);
            *(uint4*)(smem + FH_B0 + t * 16384 + SWZ((uint32_t)(m * 128 + u * 16))) = v;
        }
        FENCE_ASYNC();
        __syncthreads();
        if (tid == 0) {
            uint64_t aRh = smem_desc(sb + FH_A0),         aRl = smem_desc(sb + FH_A0 + 16384);
            uint64_t aIh = smem_desc(sb + FH_A0 + 32768), aIl = smem_desc(sb + FH_A0 + 49152);
            uint64_t bCh = smem_desc(sb + FH_B0),         bCl = smem_desc(sb + FH_B0 + 16384);
            uint32_t s1 = (INV == 0) ? 2u : 4u;
            uint32_t s2 = (INV == 0) ? 4u : 2u;
            uint64_t bS1h = smem_desc(sb + FH_B0 + s1 * 16384);
            uint64_t bS1l = smem_desc(sb + FH_B0 + s1 * 16384 + 16384);
            uint64_t bS2h = smem_desc(sb + FH_B0 + s2 * 16384);
            uint64_t bS2l = smem_desc(sb + FH_B0 + s2 * 16384 + 16384);
#pragma unroll
            for (int ks = 0; ks < 4; ks++) {
                uint64_t o = (uint64_t)ks * 2;
                uint32_t e = (c == 0 && ks == 0) ? 0u : 1u;
                mma_f16_ss(tmem, aRh + o, bCh + o, IDESC_BF16, e);
                mma_f16_ss(tmem, aRh + o, bCl + o, IDESC_BF16, 1);
                mma_f16_ss(tmem, aRl + o, bCh + o, IDESC_BF16, 1);
                mma_f16_ss(tmem, aIh + o, bS1h + o, IDESC_BF16, 1);
                mma_f16_ss(tmem, aIh + o, bS1l + o, IDESC_BF16, 1);
                mma_f16_ss(tmem, aIl + o, bS1h + o, IDESC_BF16, 1);
                mma_f16_ss(tmem + 128, aIh + o, bCh + o, IDESC_BF16, e);
                mma_f16_ss(tmem + 128, aIh + o, bCl + o, IDESC_BF16, 1);
                mma_f16_ss(tmem + 128, aIl + o, bCh + o, IDESC_BF16, 1);
                mma_f16_ss(tmem + 128, aRh + o, bS2h + o, IDESC_BF16, 1);
                mma_f16_ss(tmem + 128, aRh + o, bS2l + o, IDESC_BF16, 1);
                mma_f16_ss(tmem + 128, aRl + o, bS2h + o, IDESC_BF16, 1);
            }
            TC_COMMIT(sb + 8);
        }
        MBAR_WAIT(sb + 8, c & 1);
        __syncthreads();
    }
    TC_FENCE_AFTER();
    int half = wid >> 2;
    int dloc = (wid & 3) * 32 + lane;
    uint32_t cb = tmem + half * 128;
    float* O = half ? Oi : Or;
    size_t base = outBase + d0 + dloc;
#pragma unroll
    for (int i = 0; i < 4; i++) {
        uint32_t r[32];
        TC_LD_X32(r, cb + 32 * i);
        TC_WAIT_LD();
#pragma unroll
        for (int j = 0; j < 32; j++)
            O[base + (size_t)(32 * i + j) * outStride] = __uint_as_float(r[j]);
    }
    __syncthreads();
    if (wid == 0) TC_DEALLOC(tmem, 256);
#endif
}

// -------------------- block-diagonal complex mixing (SIMT, proven) -----------
template <int LAYER>
__global__ void k_mix(const float* __restrict__ w, const float* __restrict__ bias) {
    int l = blockIdx.z;
    int m0 = blockIdx.y * 64;
    const float* Xr = (LAYER == 1) ? g_Zr : g_Ar;
    const float* Xi = (LAYER == 1) ? g_Zi : g_Ai;
    float* Or = (LAYER == 1) ? g_Ar : g_Zr;
    float* Oi = (LAYER == 1) ? g_Ai : g_Zi;
    const float* wr = w + (size_t)l * BSv * BSv;
    const float* wi = w + (size_t)(NBv + l) * BSv * BSv;

    __shared__ float Xrs[16][64], Xis[16][64], Wrs[16][96], Wis[16][96];
    int tid = threadIdx.x, tx = tid & 15, ty = tid >> 4;
    float accr[4][6] = {}, acci[4][6] = {};
    for (int k0 = 0; k0 < BSv; k0 += 16) {
#pragma unroll
        for (int i = 0; i < 4; i++) {
            int e = tid + i * 256; int m = e >> 4, k = e & 15;
            size_t a = (size_t)(m0 + m) * Ddim + l * BSv + k0 + k;
            Xrs[k][m] = Xr[a]; Xis[k][m] = Xi[a];
        }
#pragma unroll
        for (int i = 0; i < 6; i++) {
            int e = tid + i * 256; int k = e / 96, n = e % 96;
            Wrs[k][n] = wr[(k0 + k) * BSv + n];
            Wis[k][n] = wi[(k0 + k) * BSv + n];
        }
        __syncthreads();
#pragma unroll
        for (int kk = 0; kk < 16; kk++) {
            float ar[4], ai[4], br[6], bi[6];
#pragma unroll
            for (int i = 0; i < 4; i++) { ar[i] = Xrs[kk][ty * 4 + i]; ai[i] = Xis[kk][ty * 4 + i]; }
#pragma unroll
            for (int j = 0; j < 6; j++) { br[j] = Wrs[kk][tx * 6 + j]; bi[j] = Wis[kk][tx * 6 + j]; }
#pragma unroll
            for (int i = 0; i < 4; i++)
#pragma unroll
                for (int j = 0; j < 6; j++) {
                    accr[i][j] += ar[i] * br[j] - ai[i] * bi[j];
                    acci[i][j] += ar[i] * bi[j] + ai[i] * br[j];
                }
        }
        __syncthreads();
    }
    float bre[6], bim[6];
#pragma unroll
    for (int j = 0; j < 6; j++) {
        bre[j] = bias[l * BSv + tx * 6 + j];
        bim[j] = bias[NBv * BSv + l * BSv + tx * 6 + j];
    }
#pragma unroll
    for (int i = 0; i < 4; i++) {
        size_t base = (size_t)(m0 + ty * 4 + i) * Ddim + l * BSv + tx * 6;
#pragma unroll
        for (int j = 0; j < 6; j++) {
            float r  = fmaxf(accr[i][j] + bre[j], 0.f);
            float im = fmaxf(acci[i][j] + bim[j], 0.f);
            if (LAYER == 2) { r = fmaxf(r - LAMv, 0.f); im = fmaxf(im - LAMv, 0.f); }
            Or[base + j] = r; Oi[base + j] = im;
        }
    }
}

// -------------------- tensorized irfft along W (transposed GEMM) -------------
#define FW_A0   1024
#define FW_B0   (1024 + 4 * 16384)
#define FW_SMEM (FW_B0 + 4 * 32768)
__global__ void __launch_bounds__(256, 1) k_ifftW_tc() {
#if TC_OK
    extern __shared__ char smem[];
    uint32_t sb = smem_u32(smem);
    int tid = threadIdx.x, wid = tid >> 5, lane = tid & 31;
    int z = blockIdx.y; int b = z >> 7; int h = z & 127;
    int d0 = blockIdx.x * 128;
    size_t slab = (size_t)(b * Hdim + h) * WFdim * Ddim;
    const float* Vr = g_Ar + slab;
    const float* Vi = g_Ai + slab;

    if (wid == 0) TC_ALLOC(sb, 256);
    if (tid == 0) MBAR_INIT(sb + 8, 1);
    __syncthreads();
    uint32_t tmem;
    asm volatile("ld.shared.b32 %0, [%1];" : "=r"(tmem) : "r"(sb));

    const __nv_bfloat16* gsrc[4] = {tCr_h, tCr_l, tCi_h, tCi_l};

    for (int c = 0; c < 3; c++) {
        int k0 = c * 64;
        for (int idx = tid; idx < 4096; idx += 256) {
            int kp = idx >> 7, d = idx & 127;
            int k = kp * 2;
            int g1 = k0 + k, g2 = k0 + k + 1;
            size_t ga = (size_t)g1 * Ddim + d0 + d;
            float r0 = (g1 < WFdim) ? Vr[ga] : 0.f;
            float i0 = (g1 < WFdim) ? Vi[ga] : 0.f;
            float r1 = (g2 < WFdim) ? Vr[ga + Ddim] : 0.f;
            float i1 = (g2 < WFdim) ? Vi[ga + Ddim] : 0.f;
            uint32_t sw = SWZ((uint32_t)(d * 128 + k * 2));
            *(uint32_t*)(smem + FW_A0 + sw)         = pack2(r0, r1, 0);
            *(uint32_t*)(smem + FW_A0 + 16384 + sw) = pack2(r0, r1, 1);
            *(uint32_t*)(smem + FW_A0 + 32768 + sw) = pack2(i0, i1, 0);
            *(uint32_t*)(smem + FW_A0 + 49152 + sw) = pack2(i0, i1, 1);
        }
        for (int idx = tid; idx < 8192; idx += 256) {
            int t = idx >> 11, r = idx & 2047, m = r >> 3, u = r & 7;
            uint4 v = *(const uint4*)(gsrc[t] + m * CKP + k0 + u * 8);
            *(uint4*)(smem + FW_B0 + t * 32768 + SWZ((uint32_t)(m * 128 + u * 16))) = v;
        }
        FENCE_ASYNC();
        __syncthreads();
        if (tid == 0) {
            uint64_t aRh = smem_desc(sb + FW_A0),         aRl = smem_desc(sb + FW_A0 + 16384);
            uint64_t aIh = smem_desc(sb + FW_A0 + 32768), aIl = smem_desc(sb + FW_A0 + 49152);
            uint64_t bRh = smem_desc(sb + FW_B0),          bRl = smem_desc(sb + FW_B0 + 32768);
            uint64_t bIh = smem_desc(sb + FW_B0 + 65536),  bIl = smem_desc(sb + FW_B0 + 98304);
#pragma unroll
            for (int ks = 0; ks < 4; ks++) {
                uint64_t o = (uint64_t)ks * 2;
                uint32_t e = (c == 0 && ks == 0) ? 0u : 1u;
                mma_f16_ss(tmem, aRh + o, bRh + o, IDESC_N256, e);
                mma_f16_ss(tmem, aRh + o, bRl + o, IDESC_N256, 1);
                mma_f16_ss(tmem, aRl + o, bRh + o, IDESC_N256, 1);
                mma_f16_ss(tmem, aIh + o, bIh + o, IDESC_N256, 1);
                mma_f16_ss(tmem, aIh + o, bIl + o, IDESC_N256, 1);
                mma_f16_ss(tmem, aIl + o, bIh + o, IDESC_N256, 1);
            }
            TC_COMMIT(sb + 8);
        }
        MBAR_WAIT(sb + 8, c & 1);
        __syncthreads();
    }
    TC_FENCE_AFTER();
    int half = wid >> 2;
    int dloc = (wid & 3) * 32 + lane;
    uint32_t cb = tmem + half * 128;
    size_t rowBase = (size_t)(b * 32768 + h * 256 + half * 128) * Ddim + d0 + dloc;
#pragma unroll
    for (int i = 0; i < 4; i++) {
        uint32_t r[32];
        TC_LD_X32(r, cb + 32 * i);
        TC_WAIT_LD();
#pragma unroll
        for (int j = 0; j < 32; j++)
            g_P[rowBase + (size_t)(32 * i + j) * Ddim] = __uint_as_float(r[j]);
    }
    __syncthreads();
    if (wid == 0) TC_DEALLOC(tmem, 256);
#endif
}

// -------------------- tcgen05 MLP GEMM: 256x128 tile, staged epilogue --------
#define GT_STAGES 2
#define GT_A_BYTES 32768
#define GT_B_BYTES 16384
#define GT_STAGE_BYTES (2 * GT_A_BYTES + 2 * GT_B_BYTES)
#define GT_SMEM (1024 + GT_STAGES * GT_STAGE_BYTES)

template <int EPI>
__global__ void __launch_bounds__(256, 1)
k_gemm_tc(const __grid_constant__ CUtensorMap tAh, const __grid_constant__ CUtensorMap tAl,
          const __grid_constant__ CUtensorMap tBh, const __grid_constant__ CUtensorMap tBl,
          const float* __restrict__ bias, const float* __restrict__ resid,
          float* __restrict__ outF, __nv_bfloat16* __restrict__ outHi,
          __nv_bfloat16* __restrict__ outLo, int K, int N) {
#if TC_OK
    extern __shared__ char smem[];
    uint32_t sb = smem_u32(smem);
    int tid = threadIdx.x, wid = tid >> 5, lane = tid & 31;
    int m0 = blockIdx.y * 256, n0 = blockIdx.x * 128;
    int nChunks = K >> 6;

    if (wid == 0) TC_ALLOC(sb, 256);
    if (tid == 0) {
#pragma unroll
        for (int s = 0; s < GT_STAGES; s++) { MBAR_INIT(sb + 16 + 8 * s, 1); MBAR_INIT(sb + 48 + 8 * s, 1); }
        MBAR_INIT(sb + 80, 1);
    }
    __syncthreads();
    uint32_t tmem;
    asm volatile("ld.shared.b32 %0, [%1];" : "=r"(tmem) : "r"(sb));

    if (tid == 0) {
        int s = 0, ph = 1;
        for (int c = 0; c < nChunks; c++) {
            MBAR_WAIT_RELAXED(sb + 48 + 8 * s, ph);
            MBAR_EXPECT_TX(sb + 16 + 8 * s, GT_STAGE_BYTES);
            uint32_t t0 = sb + 1024 + s * GT_STAGE_BYTES;
            TMA_LOAD_2D(t0,                               &tAh, c * 64, m0, sb + 16 + 8 * s);
            TMA_LOAD_2D(t0 + GT_A_BYTES,                  &tAl, c * 64, m0, sb + 16 + 8 * s);
            TMA_LOAD_2D(t0 + 2 * GT_A_BYTES,              &tBh, c * 64, n0, sb + 16 + 8 * s);
            TMA_LOAD_2D(t0 + 2 * GT_A_BYTES + GT_B_BYTES, &tBl, c * 64, n0, sb + 16 + 8 * s);
            if (++s == GT_STAGES) { s = 0; ph ^= 1; }
        }
    }
    if (tid == 32) {
        int s = 0, ph = 0;
        for (int c = 0; c < nChunks; c++) {
            MBAR_WAIT(sb + 16 + 8 * s, ph);
            uint32_t t0 = sb + 1024 + s * GT_STAGE_BYTES;
            uint64_t dBh = smem_desc(t0 + 2 * GT_A_BYTES);
            uint64_t dBl = smem_desc(t0 + 2 * GT_A_BYTES + GT_B_BYTES);
#pragma unroll
            for (int mb = 0; mb < 2; mb++) {
                uint64_t dAh = smem_desc(t0 + mb * 16384);
                uint64_t dAl = smem_desc(t0 + GT_A_BYTES + mb * 16384);
                uint32_t dst = tmem + mb * 128;
#pragma unroll
                for (int ks = 0; ks < 4; ks++) {
                    uint32_t en = (c > 0 || ks > 0) ? 1u : 0u;
                    mma_f16_ss(dst, dAh + ks * 2, dBh + ks * 2, IDESC_BF16, en);
                    mma_f16_ss(dst, dAh + ks * 2, dBl + ks * 2, IDESC_BF16, 1);
                    mma_f16_ss(dst, dAl + ks * 2, dBh + ks * 2, IDESC_BF16, 1);
                }
            }
            TC_COMMIT(sb + 48 + 8 * s);
            if (++s == GT_STAGES) { s = 0; ph ^= 1; }
        }
        TC_COMMIT(sb + 80);
    }

    MBAR_WAIT(sb + 80, 0);
    TC_FENCE_AFTER();

    int mb = wid >> 2;
    int mloc = mb * 128 + (wid & 3) * 32 + lane;
    uint32_t cbase = tmem + mb * 128;

    if (EPI == 0) {
        __nv_bfloat16* sHi = (__nv_bfloat16*)(smem + 1024);
        __nv_bfloat16* sLo = sHi + 256 * 130;
#pragma unroll
        for (int i = 0; i < 4; i++) {
            uint32_t r[32];
            TC_LD_X32(r, cbase + 32 * i);
            TC_WAIT_LD();
#pragma unroll
            for (int j = 0; j < 32; j++) {
                int n = n0 + 32 * i + j;
                float v = __uint_as_float(r[j]) + bias[n];
                float g = 0.5f * v * (1.f + erff(v * 0.70710678118654752f));
                __nv_bfloat16 hi, lo;
                split2(g, &hi, &lo);
                sHi[mloc * 130 + 32 * i + j] = hi;
                sLo[mloc * 130 + 32 * i + j] = lo;
            }
        }
        __syncthreads();
        const uint32_t* sHi32 = (const uint32_t*)sHi;
        const uint32_t* sLo32 = (const uint32_t*)sLo;
        uint32_t* oHi32 = (uint32_t*)outHi;
        uint32_t* oLo32 = (uint32_t*)outLo;
        int halfN = N >> 1;
        for (int idx = tid; idx < 256 * 64; idx += 256) {
            int row = idx >> 6, c = idx & 63;
            size_t o = (size_t)(m0 + row) * halfN + (n0 >> 1) + c;
            oHi32[o] = sHi32[row * 65 + c];
            oLo32[o] = sLo32[row * 65 + c];
        }
    } else {
        float* sF = (float*)(smem + 1024);
#pragma unroll
        for (int i = 0; i < 4; i++) {
            uint32_t r[32];
            TC_LD_X32(r, cbase + 32 * i);
            TC_WAIT_LD();
#pragma unroll
            for (int j = 0; j < 32; j++)
                sF[mloc * 129 + 32 * i + j] = __uint_as_float(r[j]);
        }
        __syncthreads();
        for (int idx = tid; idx < 256 * 128; idx += 256) {
            int row = idx >> 7, c = idx & 127;
            size_t o = (size_t)(m0 + row) * N + n0 + c;
            outF[o] = sF[row * 129 + c] + bias[n0 + c] + resid[o];
        }
    }
    __syncthreads();
    if (wid == 0) TC_DEALLOC(tmem, 256);
#endif
}

// -------------------- host: tensor map construction --------------------------
typedef CUresult (*EncodeFn)(CUtensorMap*, CUtensorMapDataType, cuuint32_t, void*,
                             const cuuint64_t*, const cuuint64_t*, const cuuint32_t*,
                             const cuuint32_t*, CUtensorMapInterleave, CUtensorMapSwizzle,
                             CUtensorMapL2promotion, CUtensorMapFloatOOBfill);

static void makeMap(EncodeFn enc, CUtensorMap* m, void* ptr, uint64_t d0, uint64_t d1,
                    uint32_t boxRows) {
    cuuint64_t dims[2] = {d0, d1};
    cuuint64_t strides[1] = {d0 * 2};
    cuuint32_t box[2] = {64, boxRows};
    cuuint32_t es[2] = {1, 1};
    enc(m, CU_TENSOR_MAP_DATA_TYPE_BFLOAT16, 2, ptr, dims, strides, box, es,
        CU_TENSOR_MAP_INTERLEAVE_NONE, CU_TENSOR_MAP_SWIZZLE_128B,
        CU_TENSOR_MAP_L2_PROMOTION_L2_128B, CU_TENSOR_MAP_FLOAT_OOB_FILL_NONE);
}

// ---------------------------------------------------------------------------
extern "C" void kernel_launch(void* const* d_in, const int* in_sizes, int n_in,
                              void* d_out, int out_size) {
    const float* x    = (const float*)d_in[0];
    const float* n1g  = (const float*)d_in[1];
    const float* n1b  = (const float*)d_in[2];
    const float* w1   = (const float*)d_in[3];
    const float* w2   = (const float*)d_in[4];
    const float* b1   = (const float*)d_in[5];
    const float* b2   = (const float*)d_in[6];
    const float* n2g  = (const float*)d_in[7];
    const float* n2b  = (const float*)d_in[8];
    const float* fc1w = (const float*)d_in[9];
    const float* fc1b = (const float*)d_in[10];
    const float* fc2w = (const float*)d_in[11];
    const float* fc2b = (const float*)d_in[12];
    float* out = (float*)d_out;

    float *pT, *pP;
    cudaGetSymbolAddress((void**)&pT, g_T);
    cudaGetSymbolAddress((void**)&pP, g_P);
    void *pAh, *pAl, *pHh, *pHl, *pW1h, *pW1l, *pW2h, *pW2l;
    cudaGetSymbolAddress(&pAh, gA_hi);  cudaGetSymbolAddress(&pAl, gA_lo);
    cudaGetSymbolAddress(&pHh, gH_hi);  cudaGetSymbolAddress(&pHl, gH_lo);
    cudaGetSymbolAddress(&pW1h, gW1T_hi); cudaGetSymbolAddress(&pW1l, gW1T_lo);
    cudaGetSymbolAddress(&pW2h, gW2T_hi); cudaGetSymbolAddress(&pW2l, gW2T_lo);

    EncodeFn enc = nullptr;
    cudaDriverEntryPointQueryResult qr;
    cudaGetDriverEntryPoint("cuTensorMapEncodeTiled", (void**)&enc, cudaEnableDefault, &qr);

    CUtensorMap mAh, mAl, mW1h, mW1l, mHh, mHl, mW2h, mW2l;
    makeMap(enc, &mAh, pAh, Ddim, TOKENS, 256);
    makeMap(enc, &mAl, pAl, Ddim, TOKENS, 256);
    makeMap(enc, &mW1h, pW1h, Ddim, HIDv, 128);
    makeMap(enc, &mW1l, pW1l, Ddim, HIDv, 128);
    makeMap(enc, &mHh, pHh, HIDv, TOKENS, 256);
    makeMap(enc, &mHl, pHl, HIDv, TOKENS, 256);
    makeMap(enc, &mW2h, pW2h, HIDv, Ddim, 128);
    makeMap(enc, &mW2l, pW2l, HIDv, Ddim, 128);

    cudaFuncSetAttribute(k_gemm_tc<0>, cudaFuncAttributeMaxDynamicSharedMemorySize, GT_SMEM);
    cudaFuncSetAttribute(k_gemm_tc<1>, cudaFuncAttributeMaxDynamicSharedMemorySize, GT_SMEM);
    cudaFuncSetAttribute(k_fftH_tc<0>, cudaFuncAttributeMaxDynamicSharedMemorySize, FH_SMEM);
    cudaFuncSetAttribute(k_fftH_tc<1>, cudaFuncAttributeMaxDynamicSharedMemorySize, FH_SMEM);
    cudaFuncSetAttribute(k_ifftW_tc, cudaFuncAttributeMaxDynamicSharedMemorySize, FW_SMEM);

    k_init<<<192, 256>>>();
    k_ln<0><<<TOKENS, 256>>>(x, n1g, n1b, pT, nullptr, nullptr);
    k_fftW<<<dim3(12, 1, 256), 256>>>(pT);
    k_fftH_tc<0><<<dim3(6, 258), 256, FH_SMEM>>>();
    k_mix<1><<<dim3(1, 516, 8), 256>>>(w1, b1);
    k_mix<2><<<dim3(1, 516, 8), 256>>>(w2, b2);
    k_fftH_tc<1><<<dim3(6, 258), 256, FH_SMEM>>>();
    k_ifftW_tc<<<dim3(6, 256), 256, FW_SMEM>>>();
    k_ln<1><<<TOKENS, 256>>>(pP, n2g, n2b, nullptr,
                             (__nv_bfloat16*)pAh, (__nv_bfloat16*)pAl);
    dim3 tb(32, 8);
    k_splitT<<<dim3(HIDv / 32, Ddim / 32), tb>>>(fc1w, (__nv_bfloat16*)pW1h,
                                                 (__nv_bfloat16*)pW1l, Ddim, HIDv);
    k_splitT<<<dim3(Ddim / 32, HIDv / 32), tb>>>(fc2w, (__nv_bfloat16*)pW2h,
                                                 (__nv_bfloat16*)pW2l, HIDv, Ddim);
    k_gemm_tc<0><<<dim3(HIDv / 128, TOKENS / 256), 256, GT_SMEM>>>(
        mAh, mAl, mW1h, mW1l, fc1b, nullptr, nullptr,
        (__nv_bfloat16*)pHh, (__nv_bfloat16*)pHl, Ddim, HIDv);
    k_gemm_tc<1><<<dim3(Ddim / 128, TOKENS / 256), 256, GT_SMEM>>>(
        mHh, mHl, mW2h, mW2l, fc2b, x, out, nullptr, nullptr, HIDv, Ddim);
}

// round 15
// speedup vs baseline: 1.2309x; 1.1007x over previous
#include <cuda_runtime.h>
#include <cuda_bf16.h>
#include <cuda.h>
#include <math.h>
#include <stdint.h>

// ---------------------------------------------------------------------------
// AFNO block. LN/mix SIMT fp32. fftW, fftH (fwd+inv), ifftW on tcgen05 bf16
// hi/lo (3-term) via transposed-GEMM K-major SS path (proven). fftW computes
// the Nyquist row inline during A-tile builds. MLP on tcgen05 bf16 hi/lo.
// ---------------------------------------------------------------------------

#if defined(__CUDA_ARCH__) && (defined(__CUDA_ARCH_FEAT_SM103_ALL) || \
    defined(__CUDA_ARCH_FEAT_SM100_ALL) || defined(__CUDA_ARCH_FEAT_SM101_ALL))
#define TC_OK 1
#else
#define TC_OK 0
#endif

#define Hdim   128
#define Wdim   256
#define WFdim  129
#define Ddim   768
#define NBv    8
#define BSv    96
#define HIDv   3072
#define TOKENS 65536
#define NPOSv  33024
#define LAMv   0.01f
#define CKP    192

// -------------------- scratch (device globals; no allocation) ---------------
__device__ float g_P [(size_t)TOKENS * Ddim];
__device__ float g_T [(size_t)TOKENS * Ddim];
__device__ float g_Yr[(size_t)NPOSv * Ddim];
__device__ float g_Yi[(size_t)NPOSv * Ddim];
__device__ float g_Zr[(size_t)NPOSv * Ddim];
__device__ float g_Zi[(size_t)NPOSv * Ddim];
__device__ float g_Ar[(size_t)NPOSv * Ddim];
__device__ float g_Ai[(size_t)NPOSv * Ddim];
// bf16 hi/lo operands for tensor-core MLP
__device__ __align__(1024) __nv_bfloat16 gA_hi[(size_t)TOKENS * Ddim];
__device__ __align__(1024) __nv_bfloat16 gA_lo[(size_t)TOKENS * Ddim];
__device__ __align__(1024) __nv_bfloat16 gH_hi[(size_t)TOKENS * HIDv];
__device__ __align__(1024) __nv_bfloat16 gH_lo[(size_t)TOKENS * HIDv];
__device__ __align__(1024) __nv_bfloat16 gW1T_hi[(size_t)HIDv * Ddim];
__device__ __align__(1024) __nv_bfloat16 gW1T_lo[(size_t)HIDv * Ddim];
__device__ __align__(1024) __nv_bfloat16 gW2T_hi[(size_t)Ddim * HIDv];
__device__ __align__(1024) __nv_bfloat16 gW2T_lo[(size_t)Ddim * HIDv];
// DFT tables (bf16 hi/lo, row-major [m][k])
__device__ __align__(16) __nv_bfloat16 tFc_h [Hdim * Wdim], tFc_l [Hdim * Wdim]; // [wf<128][w]
__device__ __align__(16) __nv_bfloat16 tFs_h [Hdim * Wdim], tFs_l [Hdim * Wdim];
__device__ __align__(16) __nv_bfloat16 tGc_h [Hdim * Hdim], tGc_l [Hdim * Hdim];
__device__ __align__(16) __nv_bfloat16 tGsP_h[Hdim * Hdim], tGsP_l[Hdim * Hdim];
__device__ __align__(16) __nv_bfloat16 tGsM_h[Hdim * Hdim], tGsM_l[Hdim * Hdim];
__device__ __align__(16) __nv_bfloat16 tCr_h [Wdim * CKP],  tCr_l [Wdim * CKP];
__device__ __align__(16) __nv_bfloat16 tCi_h [Wdim * CKP],  tCi_l [Wdim * CKP];

// -------------------- PTX helpers -------------------------------------------
__device__ __forceinline__ uint32_t smem_u32(const void* p) {
    uint32_t a;
    asm("{ .reg .u64 t; cvta.to.shared.u64 t, %1; cvt.u32.u64 %0, t; }" : "=r"(a) : "l"(p));
    return a;
}
#define MBAR_INIT(a, c) \
    asm volatile("mbarrier.init.shared.b64 [%0], %1;" :: "r"(a), "r"(c) : "memory")
#define MBAR_EXPECT_TX(a, b) \
    asm volatile("mbarrier.arrive.expect_tx.shared.b64 _, [%0], %1;" :: "r"(a), "r"(b) : "memory")
#define MBAR_WAIT(a, ph) do { \
    uint32_t _m = (a), _p = (ph), _d; \
    asm volatile("{\n\t.reg .pred p;\n\t" \
        "mbarrier.try_wait.parity.acquire.cta.shared::cta.b64 p, [%1], %2;\n\t" \
        "selp.b32 %0, 1, 0, p;\n\t}" : "=r"(_d) : "r"(_m), "r"(_p) : "memory"); \
    if (!_d) { asm volatile("{\n\t.reg .pred P1;\n\tWL%=:\n\t" \
        "mbarrier.try_wait.parity.acquire.cta.shared::cta.b64 P1, [%0], %1, 0x989680;\n\t" \
        "@P1 bra.uni WD%=;\n\tbra.uni WL%=;\n\tWD%=:\n\t}" :: "r"(_m), "r"(_p) : "memory"); } \
} while(0)
#define MBAR_WAIT_RELAXED(a, ph) do { \
    uint32_t _m = (a), _p = (ph), _d; \
    asm volatile("{\n\t.reg .pred p;\n\t" \
        "mbarrier.try_wait.parity.relaxed.cta.shared::cta.b64 p, [%1], %2, 0x989680;\n\t" \
        "selp.b32 %0, 1, 0, p;\n\t}" : "=r"(_d) : "r"(_m), "r"(_p) : "memory"); \
    if (!_d) { asm volatile("{\n\t.reg .pred P1;\n\tWL%=:\n\t" \
        "mbarrier.try_wait.parity.relaxed.cta.shared::cta.b64 P1, [%0], %1, 0x989680;\n\t" \
        "@P1 bra.uni WD%=;\n\tbra.uni WL%=;\n\tWD%=:\n\t}" :: "r"(_m), "r"(_p) : "memory"); } \
} while(0)
#define TMA_LOAD_2D(dst, map, cx, cy, mbar) \
    asm volatile("cp.async.bulk.tensor.2d.shared::cta.global.tile.mbarrier::complete_tx::bytes " \
        "[%0], [%1, {%2, %3}], [%4];" \
        :: "r"(dst), "l"(map), "r"(cx), "r"(cy), "r"(mbar) : "memory")
#define TC_ALLOC(sm, n) \
    asm volatile("tcgen05.alloc.cta_group::1.sync.aligned.shared::cta.b32 [%0], %1;" \
        :: "r"(sm), "r"(n) : "memory")
#define TC_DEALLOC(t, n) \
    asm volatile("tcgen05.dealloc.cta_group::1.sync.aligned.b32 %0, %1;" :: "r"(t), "r"(n))
#define TC_COMMIT(mbar) \
    asm volatile("tcgen05.commit.cta_group::1.mbarrier::arrive::one.shared::cluster.b64 [%0];" \
        :: "r"(mbar) : "memory")
#define TC_FENCE_AFTER() asm volatile("tcgen05.fence::after_thread_sync;" ::: "memory")
#define TC_WAIT_LD() asm volatile("tcgen05.wait::ld.sync.aligned;" ::: "memory")
#define FENCE_ASYNC() asm volatile("fence.proxy.async.shared::cta;" ::: "memory")
#define TC_LD_X32(r, addr) \
    asm volatile("tcgen05.ld.sync.aligned.32x32b.x32.b32 " \
        "{%0,%1,%2,%3,%4,%5,%6,%7,%8,%9,%10,%11,%12,%13,%14,%15," \
        "%16,%17,%18,%19,%20,%21,%22,%23,%24,%25,%26,%27,%28,%29,%30,%31}, [%32];" \
        : "=r"((r)[0]),"=r"((r)[1]),"=r"((r)[2]),"=r"((r)[3]),"=r"((r)[4]),"=r"((r)[5]), \
          "=r"((r)[6]),"=r"((r)[7]),"=r"((r)[8]),"=r"((r)[9]),"=r"((r)[10]),"=r"((r)[11]), \
          "=r"((r)[12]),"=r"((r)[13]),"=r"((r)[14]),"=r"((r)[15]),"=r"((r)[16]),"=r"((r)[17]), \
          "=r"((r)[18]),"=r"((r)[19]),"=r"((r)[20]),"=r"((r)[21]),"=r"((r)[22]),"=r"((r)[23]), \
          "=r"((r)[24]),"=r"((r)[25]),"=r"((r)[26]),"=r"((r)[27]),"=r"((r)[28]),"=r"((r)[29]), \
          "=r"((r)[30]),"=r"((r)[31]) : "r"(addr))

__device__ __forceinline__ void mma_f16_ss(uint32_t d, uint64_t ad, uint64_t bd,
                                           uint32_t idesc, uint32_t en) {
#if TC_OK
    asm volatile("{\n\t.reg .pred p;\n\tsetp.ne.u32 p, %4, 0;\n\t"
        "tcgen05.mma.cta_group::1.kind::f16 [%0], %1, %2, %3, {%5, %5, %5, %5}, p;\n\t}"
        :: "r"(d), "l"(ad), "l"(bd), "r"(idesc), "r"(en), "r"(0u) : "memory");
#endif
}
// K-major SW128 desc (LBO=1, SBO=64) — the proven layout
__device__ __forceinline__ uint64_t smem_desc(uint32_t addr) {
    return ((uint64_t)2 << 61) | ((uint64_t)1 << 46) | ((uint64_t)64 << 32)
         | ((uint64_t)1 << 16) | (uint64_t)((addr >> 4) & 0x3FFF);
}
__device__ __forceinline__ void split2(float v, __nv_bfloat16* h, __nv_bfloat16* l) {
    *h = __float2bfloat16_rn(v);
    *l = __float2bfloat16_rn(v - __bfloat162float(*h));
}
__device__ __forceinline__ uint32_t pack2(float v0, float v1, int lo) {
    __nv_bfloat16 h0, l0, h1, l1;
    split2(v0, &h0, &l0); split2(v1, &h1, &l1);
    __nv_bfloat16 a = lo ? l0 : h0, b = lo ? l1 : h1;
    return (uint32_t)__bfloat16_as_ushort(a) | ((uint32_t)__bfloat16_as_ushort(b) << 16);
}
#define SWZ(x) ((x) ^ (((x) >> 3) & 0x70))

#define IDESC_BF16 ((1u << 4) | (1u << 7) | (1u << 10) | (16u << 17) | (8u << 24))
#define IDESC_N256 ((1u << 4) | (1u << 7) | (1u << 10) | (32u << 17) | (8u << 24))

// -------------------- DFT table init ----------------------------------------
__global__ void k_init() {
    int i = blockIdx.x * 256 + threadIdx.x;
    const double PI2 = 6.283185307179586476925286766559;
    const double S = sqrt(32768.0);
    if (i < Hdim * Wdim) {             // fftW tables [wf<128][w]
        int wf = i >> 8, w = i & 255;
        double th = PI2 * (double)((wf * w) % Wdim) / (double)Wdim;
        split2((float)( cos(th) / S), &tFc_h[i], &tFc_l[i]);
        split2((float)(-sin(th) / S), &tFs_h[i], &tFs_l[i]);
    }
    if (i < Hdim * Hdim) {
        int m = i >> 7, k = i & 127;
        double ph = PI2 * (double)((m * k) % Hdim) / (double)Hdim;
        float cv = (float)cos(ph), sv = (float)sin(ph);
        split2(cv,  &tGc_h[i],  &tGc_l[i]);
        split2(sv,  &tGsP_h[i], &tGsP_l[i]);
        split2(-sv, &tGsM_h[i], &tGsM_l[i]);
    }
    if (i < Wdim * CKP) {
        int w = i / CKP, wf = i % CKP;
        float cr = 0.f, ci = 0.f;
        if (wf < WFdim) {
            double th = PI2 * (double)((wf * w) % Wdim) / (double)Wdim;
            double a = (wf == 0 || wf == Wdim / 2) ? 1.0 : 2.0;
            cr = (float)( a * cos(th) / S);
            ci = (float)(-a * sin(th) / S);
        }
        split2(cr, &tCr_h[i], &tCr_l[i]);
        split2(ci, &tCi_h[i], &tCi_l[i]);
    }
}

// -------------------- LayerNorm (SPLIT=1: emit bf16 hi/lo) -------------------
template <int SPLIT>
__global__ void k_ln(const float* __restrict__ in, const float* __restrict__ gam,
                     const float* __restrict__ bet, float* __restrict__ out,
                     __nv_bfloat16* __restrict__ ohi, __nv_bfloat16* __restrict__ olo) {
    int t = blockIdx.x;
    const float* xp = in + (size_t)t * Ddim;
    int tid = threadIdx.x;
    float v[3], s = 0.f, s2 = 0.f;
#pragma unroll
    for (int i = 0; i < 3; i++) { v[i] = xp[tid + i * 256]; s += v[i]; s2 += v[i] * v[i]; }
#pragma unroll
    for (int o = 16; o; o >>= 1) {
        s  += __shfl_xor_sync(0xffffffffu, s,  o);
        s2 += __shfl_xor_sync(0xffffffffu, s2, o);
    }
    __shared__ float sh[2][8];
    __shared__ float mu_s, rs_s;
    int w = tid >> 5;
    if ((tid & 31) == 0) { sh[0][w] = s; sh[1][w] = s2; }
    __syncthreads();
    if (tid == 0) {
        float ts = 0.f, ts2 = 0.f;
#pragma unroll
        for (int i = 0; i < 8; i++) { ts += sh[0][i]; ts2 += sh[1][i]; }
        float mu = ts * (1.f / 768.f);
        float var = ts2 * (1.f / 768.f) - mu * mu;
        mu_s = mu; rs_s = rsqrtf(var + 1e-5f);
    }
    __syncthreads();
    float mu = mu_s, rs = rs_s;
#pragma unroll
    for (int i = 0; i < 3; i++) {
        int c = tid + i * 256;
        float r = (v[i] - mu) * rs * gam[c] + bet[c];
        if (SPLIT == 0) {
            out[(size_t)t * Ddim + c] = r;
        } else {
            __nv_bfloat16 hi, lo;
            split2(r, &hi, &lo);
            ohi[(size_t)t * Ddim + c] = hi;
            olo[(size_t)t * Ddim + c] = lo;
        }
    }
}

// -------------------- transpose + split weights ------------------------------
__global__ void k_splitT(const float* __restrict__ in, __nv_bfloat16* __restrict__ oh,
                         __nv_bfloat16* __restrict__ ol, int R, int C) {
    __shared__ float t[32][33];
    int c0 = blockIdx.x * 32, r0 = blockIdx.y * 32;
    int x = threadIdx.x, y = threadIdx.y;
#pragma unroll
    for (int i = 0; i < 32; i += 8)
        t[y + i][x] = in[(size_t)(r0 + y + i) * C + c0 + x];
    __syncthreads();
#pragma unroll
    for (int i = 0; i < 32; i += 8) {
        __nv_bfloat16 hi, lo;
        split2(t[x][y + i], &hi, &lo);
        size_t o = (size_t)(c0 + y + i) * R + r0 + x;
        oh[o] = hi; ol[o] = lo;
    }
}

// -------------------- tensorized rfft along W (transposed GEMM) --------------
// YrT[d,wf] = sum_w xT[d,w]·Fc[wf,w], YiT[d,wf] = sum_w xT[d,w]·Fs[wf,w].
// A = x transposed (hi/lo, real only), B = Fc/Fs tables. K=256 in 4 chunks.
// Nyquist (wf=128) accumulated inline during A builds (each (w,d) read once).
#define FWD_A0   1024
#define FWD_B0   (1024 + 2 * 16384)
#define FWD_SMEM (FWD_B0 + 4 * 16384)     // 99328
__global__ void __launch_bounds__(256, 1) k_fftW_tc(const float* __restrict__ X) {
#if TC_OK
    extern __shared__ char smem[];
    uint32_t sb = smem_u32(smem);
    int tid = threadIdx.x, wid = tid >> 5, lane = tid & 31;
    int z = blockIdx.y; int b = z >> 7; int h = z & 127;
    int d0 = blockIdx.x * 128;
    const float* Xp = X + (size_t)(b * 32768 + h * 256) * Ddim;

    if (wid == 0) TC_ALLOC(sb, 256);
    if (tid == 0) MBAR_INIT(sb + 8, 1);
    __syncthreads();
    uint32_t tmem;
    asm volatile("ld.shared.b32 %0, [%1];" : "=r"(tmem) : "r"(sb));

    const __nv_bfloat16* gsrc[4] = {tFc_h, tFc_l, tFs_h, tFs_l};
    float nyq = 0.f;

    for (int c = 0; c < 4; c++) {
        int k0 = c * 64;
        // A: transpose x 64w x 128d -> rows d (K-major SW128), pair-packed
        for (int idx = tid; idx < 4096; idx += 256) {
            int wp = idx >> 7, d = idx & 127;
            int w = wp * 2;
            size_t g = (size_t)(k0 + w) * Ddim + d0 + d;
            float v0 = Xp[g], v1 = Xp[g + Ddim];
            nyq += v0 - v1;                    // (k0+w) even, next odd
            uint32_t sw = SWZ((uint32_t)(d * 128 + w * 2));
            *(uint32_t*)(smem + FWD_A0 + sw)         = pack2(v0, v1, 0);
            *(uint32_t*)(smem + FWD_A0 + 16384 + sw) = pack2(v0, v1, 1);
        }
        // B: Fc/Fs table slices [128 wf][64 w]
        for (int idx = tid; idx < 4096; idx += 256) {
            int t = idx >> 10, r = idx & 1023, m = r >> 3, u = r & 7;
            uint4 v = *(const uint4*)(gsrc[t] + m * Wdim + k0 + u * 8);
            *(uint4*)(smem + FWD_B0 + t * 16384 + SWZ((uint32_t)(m * 128 + u * 16))) = v;
        }
        FENCE_ASYNC();
        __syncthreads();
        if (tid == 0) {
            uint64_t aH = smem_desc(sb + FWD_A0), aL = smem_desc(sb + FWD_A0 + 16384);
            uint64_t bCh = smem_desc(sb + FWD_B0),         bCl = smem_desc(sb + FWD_B0 + 16384);
            uint64_t bSh = smem_desc(sb + FWD_B0 + 32768), bSl = smem_desc(sb + FWD_B0 + 49152);
#pragma unroll
            for (int ks = 0; ks < 4; ks++) {
                uint64_t o = (uint64_t)ks * 2;
                uint32_t e = (c == 0 && ks == 0) ? 0u : 1u;
                mma_f16_ss(tmem,       aH + o, bCh + o, IDESC_BF16, e);
                mma_f16_ss(tmem,       aH + o, bCl + o, IDESC_BF16, 1);
                mma_f16_ss(tmem,       aL + o, bCh + o, IDESC_BF16, 1);
                mma_f16_ss(tmem + 128, aH + o, bSh + o, IDESC_BF16, e);
                mma_f16_ss(tmem + 128, aH + o, bSl + o, IDESC_BF16, 1);
                mma_f16_ss(tmem + 128, aL + o, bSh + o, IDESC_BF16, 1);
            }
            TC_COMMIT(sb + 8);
        }
        MBAR_WAIT(sb + 8, c & 1);
        __syncthreads();
    }
    TC_FENCE_AFTER();
    // Nyquist: thread's d is invariant (d = tid & 127); 2 threads per d.
    float* red = (float*)(smem + FWD_A0);
    red[tid] = nyq;
    __syncthreads();
    if (tid < 128) {
        float s = red[tid] + red[tid + 128];
        size_t base = ((size_t)(b * WFdim + 128) * Hdim + h) * Ddim + d0 + tid;
        g_Yr[base] = s * (1.f / 181.01933598375617f);
        g_Yi[base] = 0.f;
    }
    // epilogue: warps 0-3 -> Yr (cols 0-127), 4-7 -> Yi; lane dim = d
    int half = wid >> 2;
    int dloc = (wid & 3) * 32 + lane;
    uint32_t cb = tmem + half * 128;
    float* O = half ? g_Yi : g_Yr;
    size_t base = ((size_t)b * WFdim * Hdim + h) * Ddim + d0 + dloc;
    size_t stride = (size_t)Hdim * Ddim;
#pragma unroll
    for (int i = 0; i < 4; i++) {
        uint32_t r[32];
        TC_LD_X32(r, cb + 32 * i);
        TC_WAIT_LD();
#pragma unroll
        for (int j = 0; j < 32; j++)
            O[base + (size_t)(32 * i + j) * stride] = __uint_as_float(r[j]);
    }
    __syncthreads();
    if (wid == 0) TC_DEALLOC(tmem, 256);
#endif
}

// -------------------- tensorized complex FFT along H (transposed GEMM) -------
#define FH_A0   1024
#define FH_B0   (1024 + 4 * 16384)
#define FH_SMEM (FH_B0 + 6 * 16384)
template <int INV>
__global__ void __launch_bounds__(256, 1) k_fftH_tc() {
#if TC_OK
    extern __shared__ char smem[];
    uint32_t sb = smem_u32(smem);
    int tid = threadIdx.x, wid = tid >> 5, lane = tid & 31;
    int z = blockIdx.y; int b = z / WFdim; int wf = z % WFdim;
    int d0 = blockIdx.x * 128;
    size_t slab = (size_t)(b * WFdim + wf) * Hdim * Ddim;
    const float* Br = (INV == 0) ? (g_Yr + slab) : (g_Zr + slab);
    const float* Bi = (INV == 0) ? (g_Yi + slab) : (g_Zi + slab);
    float* Or = (INV == 0) ? g_Zr : g_Ar;
    float* Oi = (INV == 0) ? g_Zi : g_Ai;
    size_t outBase = (INV == 0) ? slab : ((size_t)b * Hdim * WFdim + wf) * Ddim;
    size_t outStride = (INV == 0) ? (size_t)Ddim : (size_t)WFdim * Ddim;

    if (wid == 0) TC_ALLOC(sb, 256);
    if (tid == 0) MBAR_INIT(sb + 8, 1);
    __syncthreads();
    uint32_t tmem;
    asm volatile("ld.shared.b32 %0, [%1];" : "=r"(tmem) : "r"(sb));

    const __nv_bfloat16* gsrc[6] = {tGc_h, tGc_l, tGsP_h, tGsP_l, tGsM_h, tGsM_l};

    for (int c = 0; c < 2; c++) {
        int k0 = c * 64;
        for (int idx = tid; idx < 4096; idx += 256) {
            int hp = idx >> 7, d = idx & 127;
            int h = hp * 2;
            size_t g0 = (size_t)(k0 + h) * Ddim + d0 + d;
            float r0 = Br[g0], r1 = Br[g0 + Ddim];
            float i0 = Bi[g0], i1 = Bi[g0 + Ddim];
            uint32_t sw = SWZ((uint32_t)(d * 128 + h * 2));
            *(uint32_t*)(smem + FH_A0 + sw)         = pack2(r0, r1, 0);
            *(uint32_t*)(smem + FH_A0 + 16384 + sw) = pack2(r0, r1, 1);
            *(uint32_t*)(smem + FH_A0 + 32768 + sw) = pack2(i0, i1, 0);
            *(uint32_t*)(smem + FH_A0 + 49152 + sw) = pack2(i0, i1, 1);
        }
        for (int idx = tid; idx < 6144; idx += 256) {
            int t = idx >> 10, r = idx & 1023, m = r >> 3, u = r & 7;
            uint4 v = *(const uint4*)(gsrc[t] + m * Hdim + k0 + u * 8);
            *(uint4*)(smem + FH_B0 + t * 16384 + SWZ((uint32_t)(m * 128 + u * 16))) = v;
        }
        FENCE_ASYNC();
        __syncthreads();
        if (tid == 0) {
            uint64_t aRh = smem_desc(sb + FH_A0),         aRl = smem_desc(sb + FH_A0 + 16384);
            uint64_t aIh = smem_desc(sb + FH_A0 + 32768), aIl = smem_desc(sb + FH_A0 + 49152);
            uint64_t bCh = smem_desc(sb + FH_B0),         bCl = smem_desc(sb + FH_B0 + 16384);
            uint32_t s1 = (INV == 0) ? 2u : 4u;
            uint32_t s2 = (INV == 0) ? 4u : 2u;
            uint64_t bS1h = smem_desc(sb + FH_B0 + s1 * 16384);
            uint64_t bS1l = smem_desc(sb + FH_B0 + s1 * 16384 + 16384);
            uint64_t bS2h = smem_desc(sb + FH_B0 + s2 * 16384);
            uint64_t bS2l = smem_desc(sb + FH_B0 + s2 * 16384 + 16384);
#pragma unroll
            for (int ks = 0; ks < 4; ks++) {
                uint64_t o = (uint64_t)ks * 2;
                uint32_t e = (c == 0 && ks == 0) ? 0u : 1u;
                mma_f16_ss(tmem, aRh + o, bCh + o, IDESC_BF16, e);
                mma_f16_ss(tmem, aRh + o, bCl + o, IDESC_BF16, 1);
                mma_f16_ss(tmem, aRl + o, bCh + o, IDESC_BF16, 1);
                mma_f16_ss(tmem, aIh + o, bS1h + o, IDESC_BF16, 1);
                mma_f16_ss(tmem, aIh + o, bS1l + o, IDESC_BF16, 1);
                mma_f16_ss(tmem, aIl + o, bS1h + o, IDESC_BF16, 1);
                mma_f16_ss(tmem + 128, aIh + o, bCh + o, IDESC_BF16, e);
                mma_f16_ss(tmem + 128, aIh + o, bCl + o, IDESC_BF16, 1);
                mma_f16_ss(tmem + 128, aIl + o, bCh + o, IDESC_BF16, 1);
                mma_f16_ss(tmem + 128, aRh + o, bS2h + o, IDESC_BF16, 1);
                mma_f16_ss(tmem + 128, aRh + o, bS2l + o, IDESC_BF16, 1);
                mma_f16_ss(tmem + 128, aRl + o, bS2h + o, IDESC_BF16, 1);
            }
            TC_COMMIT(sb + 8);
        }
        MBAR_WAIT(sb + 8, c & 1);
        __syncthreads();
    }
    TC_FENCE_AFTER();
    int half = wid >> 2;
    int dloc = (wid & 3) * 32 + lane;
    uint32_t cb = tmem + half * 128;
    float* O = half ? Oi : Or;
    size_t base = outBase + d0 + dloc;
#pragma unroll
    for (int i = 0; i < 4; i++) {
        uint32_t r[32];
        TC_LD_X32(r, cb + 32 * i);
        TC_WAIT_LD();
#pragma unroll
        for (int j = 0; j < 32; j++)
            O[base + (size_t)(32 * i + j) * outStride] = __uint_as_float(r[j]);
    }
    __syncthreads();
    if (wid == 0) TC_DEALLOC(tmem, 256);
#endif
}

// -------------------- block-diagonal complex mixing (SIMT, proven) -----------
template <int LAYER>
__global__ void k_mix(const float* __restrict__ w, const float* __restrict__ bias) {
    int l = blockIdx.z;
    int m0 = blockIdx.y * 64;
    const float* Xr = (LAYER == 1) ? g_Zr : g_Ar;
    const float* Xi = (LAYER == 1) ? g_Zi : g_Ai;
    float* Or = (LAYER == 1) ? g_Ar : g_Zr;
    float* Oi = (LAYER == 1) ? g_Ai : g_Zi;
    const float* wr = w + (size_t)l * BSv * BSv;
    const float* wi = w + (size_t)(NBv + l) * BSv * BSv;

    __shared__ float Xrs[16][64], Xis[16][64], Wrs[16][96], Wis[16][96];
    int tid = threadIdx.x, tx = tid & 15, ty = tid >> 4;
    float accr[4][6] = {}, acci[4][6] = {};
    for (int k0 = 0; k0 < BSv; k0 += 16) {
#pragma unroll
        for (int i = 0; i < 4; i++) {
            int e = tid + i * 256; int m = e >> 4, k = e & 15;
            size_t a = (size_t)(m0 + m) * Ddim + l * BSv + k0 + k;
            Xrs[k][m] = Xr[a]; Xis[k][m] = Xi[a];
        }
#pragma unroll
        for (int i = 0; i < 6; i++) {
            int e = tid + i * 256; int k = e / 96, n = e % 96;
            Wrs[k][n] = wr[(k0 + k) * BSv + n];
            Wis[k][n] = wi[(k0 + k) * BSv + n];
        }
        __syncthreads();
#pragma unroll
        for (int kk = 0; kk < 16; kk++) {
            float ar[4], ai[4], br[6], bi[6];
#pragma unroll
            for (int i = 0; i < 4; i++) { ar[i] = Xrs[kk][ty * 4 + i]; ai[i] = Xis[kk][ty * 4 + i]; }
#pragma unroll
            for (int j = 0; j < 6; j++) { br[j] = Wrs[kk][tx * 6 + j]; bi[j] = Wis[kk][tx * 6 + j]; }
#pragma unroll
            for (int i = 0; i < 4; i++)
#pragma unroll
                for (int j = 0; j < 6; j++) {
                    accr[i][j] += ar[i] * br[j] - ai[i] * bi[j];
                    acci[i][j] += ar[i] * bi[j] + ai[i] * br[j];
                }
        }
        __syncthreads();
    }
    float bre[6], bim[6];
#pragma unroll
    for (int j = 0; j < 6; j++) {
        bre[j] = bias[l * BSv + tx * 6 + j];
        bim[j] = bias[NBv * BSv + l * BSv + tx * 6 + j];
    }
#pragma unroll
    for (int i = 0; i < 4; i++) {
        size_t base = (size_t)(m0 + ty * 4 + i) * Ddim + l * BSv + tx * 6;
#pragma unroll
        for (int j = 0; j < 6; j++) {
            float r  = fmaxf(accr[i][j] + bre[j], 0.f);
            float im = fmaxf(acci[i][j] + bim[j], 0.f);
            if (LAYER == 2) { r = fmaxf(r - LAMv, 0.f); im = fmaxf(im - LAMv, 0.f); }
            Or[base + j] = r; Oi[base + j] = im;
        }
    }
}

// -------------------- tensorized irfft along W (transposed GEMM) -------------
#define FW_A0   1024
#define FW_B0   (1024 + 4 * 16384)
#define FW_SMEM (FW_B0 + 4 * 32768)
__global__ void __launch_bounds__(256, 1) k_ifftW_tc() {
#if TC_OK
    extern __shared__ char smem[];
    uint32_t sb = smem_u32(smem);
    int tid = threadIdx.x, wid = tid >> 5, lane = tid & 31;
    int z = blockIdx.y; int b = z >> 7; int h = z & 127;
    int d0 = blockIdx.x * 128;
    size_t slab = (size_t)(b * Hdim + h) * WFdim * Ddim;
    const float* Vr = g_Ar + slab;
    const float* Vi = g_Ai + slab;

    if (wid == 0) TC_ALLOC(sb, 256);
    if (tid == 0) MBAR_INIT(sb + 8, 1);
    __syncthreads();
    uint32_t tmem;
    asm volatile("ld.shared.b32 %0, [%1];" : "=r"(tmem) : "r"(sb));

    const __nv_bfloat16* gsrc[4] = {tCr_h, tCr_l, tCi_h, tCi_l};

    for (int c = 0; c < 3; c++) {
        int k0 = c * 64;
        for (int idx = tid; idx < 4096; idx += 256) {
            int kp = idx >> 7, d = idx & 127;
            int k = kp * 2;
            int g1 = k0 + k, g2 = k0 + k + 1;
            size_t ga = (size_t)g1 * Ddim + d0 + d;
            float r0 = (g1 < WFdim) ? Vr[ga] : 0.f;
            float i0 = (g1 < WFdim) ? Vi[ga] : 0.f;
            float r1 = (g2 < WFdim) ? Vr[ga + Ddim] : 0.f;
            float i1 = (g2 < WFdim) ? Vi[ga + Ddim] : 0.f;
            uint32_t sw = SWZ((uint32_t)(d * 128 + k * 2));
            *(uint32_t*)(smem + FW_A0 + sw)         = pack2(r0, r1, 0);
            *(uint32_t*)(smem + FW_A0 + 16384 + sw) = pack2(r0, r1, 1);
            *(uint32_t*)(smem + FW_A0 + 32768 + sw) = pack2(i0, i1, 0);
            *(uint32_t*)(smem + FW_A0 + 49152 + sw) = pack2(i0, i1, 1);
        }
        for (int idx = tid; idx < 8192; idx += 256) {
            int t = idx >> 11, r = idx & 2047, m = r >> 3, u = r & 7;
            uint4 v = *(const uint4*)(gsrc[t] + m * CKP + k0 + u * 8);
            *(uint4*)(smem + FW_B0 + t * 32768 + SWZ((uint32_t)(m * 128 + u * 16))) = v;
        }
        FENCE_ASYNC();
        __syncthreads();
        if (tid == 0) {
            uint64_t aRh = smem_desc(sb + FW_A0),         aRl = smem_desc(sb + FW_A0 + 16384);
            uint64_t aIh = smem_desc(sb + FW_A0 + 32768), aIl = smem_desc(sb + FW_A0 + 49152);
            uint64_t bRh = smem_desc(sb + FW_B0),          bRl = smem_desc(sb + FW_B0 + 32768);
            uint64_t bIh = smem_desc(sb + FW_B0 + 65536),  bIl = smem_desc(sb + FW_B0 + 98304);
#pragma unroll
            for (int ks = 0; ks < 4; ks++) {
                uint64_t o = (uint64_t)ks * 2;
                uint32_t e = (c == 0 && ks == 0) ? 0u : 1u;
                mma_f16_ss(tmem, aRh + o, bRh + o, IDESC_N256, e);
                mma_f16_ss(tmem, aRh + o, bRl + o, IDESC_N256, 1);
                mma_f16_ss(tmem, aRl + o, bRh + o, IDESC_N256, 1);
                mma_f16_ss(tmem, aIh + o, bIh + o, IDESC_N256, 1);
                mma_f16_ss(tmem, aIh + o, bIl + o, IDESC_N256, 1);
                mma_f16_ss(tmem, aIl + o, bIh + o, IDESC_N256, 1);
            }
            TC_COMMIT(sb + 8);
        }
        MBAR_WAIT(sb + 8, c & 1);
        __syncthreads();
    }
    TC_FENCE_AFTER();
    int half = wid >> 2;
    int dloc = (wid & 3) * 32 + lane;
    uint32_t cb = tmem + half * 128;
    size_t rowBase = (size_t)(b * 32768 + h * 256 + half * 128) * Ddim + d0 + dloc;
#pragma unroll
    for (int i = 0; i < 4; i++) {
        uint32_t r[32];
        TC_LD_X32(r, cb + 32 * i);
        TC_WAIT_LD();
#pragma unroll
        for (int j = 0; j < 32; j++)
            g_P[rowBase + (size_t)(32 * i + j) * Ddim] = __uint_as_float(r[j]);
    }
    __syncthreads();
    if (wid == 0) TC_DEALLOC(tmem, 256);
#endif
}

// -------------------- tcgen05 MLP GEMM: 256x128 tile, staged epilogue --------
#define GT_STAGES 2
#define GT_A_BYTES 32768
#define GT_B_BYTES 16384
#define GT_STAGE_BYTES (2 * GT_A_BYTES + 2 * GT_B_BYTES)
#define GT_SMEM (1024 + GT_STAGES * GT_STAGE_BYTES)

template <int EPI>
__global__ void __launch_bounds__(256, 1)
k_gemm_tc(const __grid_constant__ CUtensorMap tAh, const __grid_constant__ CUtensorMap tAl,
          const __grid_constant__ CUtensorMap tBh, const __grid_constant__ CUtensorMap tBl,
          const float* __restrict__ bias, const float* __restrict__ resid,
          float* __restrict__ outF, __nv_bfloat16* __restrict__ outHi,
          __nv_bfloat16* __restrict__ outLo, int K, int N) {
#if TC_OK
    extern __shared__ char smem[];
    uint32_t sb = smem_u32(smem);
    int tid = threadIdx.x, wid = tid >> 5, lane = tid & 31;
    int m0 = blockIdx.y * 256, n0 = blockIdx.x * 128;
    int nChunks = K >> 6;

    if (wid == 0) TC_ALLOC(sb, 256);
    if (tid == 0) {
#pragma unroll
        for (int s = 0; s < GT_STAGES; s++) { MBAR_INIT(sb + 16 + 8 * s, 1); MBAR_INIT(sb + 48 + 8 * s, 1); }
        MBAR_INIT(sb + 80, 1);
    }
    __syncthreads();
    uint32_t tmem;
    asm volatile("ld.shared.b32 %0, [%1];" : "=r"(tmem) : "r"(sb));

    if (tid == 0) {
        int s = 0, ph = 1;
        for (int c = 0; c < nChunks; c++) {
            MBAR_WAIT_RELAXED(sb + 48 + 8 * s, ph);
            MBAR_EXPECT_TX(sb + 16 + 8 * s, GT_STAGE_BYTES);
            uint32_t t0 = sb + 1024 + s * GT_STAGE_BYTES;
            TMA_LOAD_2D(t0,                               &tAh, c * 64, m0, sb + 16 + 8 * s);
            TMA_LOAD_2D(t0 + GT_A_BYTES,                  &tAl, c * 64, m0, sb + 16 + 8 * s);
            TMA_LOAD_2D(t0 + 2 * GT_A_BYTES,              &tBh, c * 64, n0, sb + 16 + 8 * s);
            TMA_LOAD_2D(t0 + 2 * GT_A_BYTES + GT_B_BYTES, &tBl, c * 64, n0, sb + 16 + 8 * s);
            if (++s == GT_STAGES) { s = 0; ph ^= 1; }
        }
    }
    if (tid == 32) {
        int s = 0, ph = 0;
        for (int c = 0; c < nChunks; c++) {
            MBAR_WAIT(sb + 16 + 8 * s, ph);
            uint32_t t0 = sb + 1024 + s * GT_STAGE_BYTES;
            uint64_t dBh = smem_desc(t0 + 2 * GT_A_BYTES);
            uint64_t dBl = smem_desc(t0 + 2 * GT_A_BYTES + GT_B_BYTES);
#pragma unroll
            for (int mb = 0; mb < 2; mb++) {
                uint64_t dAh = smem_desc(t0 + mb * 16384);
                uint64_t dAl = smem_desc(t0 + GT_A_BYTES + mb * 16384);
                uint32_t dst = tmem + mb * 128;
#pragma unroll
                for (int ks = 0; ks < 4; ks++) {
                    uint32_t en = (c > 0 || ks > 0) ? 1u : 0u;
                    mma_f16_ss(dst, dAh + ks * 2, dBh + ks * 2, IDESC_BF16, en);
                    mma_f16_ss(dst, dAh + ks * 2, dBl + ks * 2, IDESC_BF16, 1);
                    mma_f16_ss(dst, dAl + ks * 2, dBh + ks * 2, IDESC_BF16, 1);
                }
            }
            TC_COMMIT(sb + 48 + 8 * s);
            if (++s == GT_STAGES) { s = 0; ph ^= 1; }
        }
        TC_COMMIT(sb + 80);
    }

    MBAR_WAIT(sb + 80, 0);
    TC_FENCE_AFTER();

    int mb = wid >> 2;
    int mloc = mb * 128 + (wid & 3) * 32 + lane;
    uint32_t cbase = tmem + mb * 128;

    if (EPI == 0) {
        __nv_bfloat16* sHi = (__nv_bfloat16*)(smem + 1024);
        __nv_bfloat16* sLo = sHi + 256 * 130;
#pragma unroll
        for (int i = 0; i < 4; i++) {
            uint32_t r[32];
            TC_LD_X32(r, cbase + 32 * i);
            TC_WAIT_LD();
#pragma unroll
            for (int j = 0; j < 32; j++) {
                int n = n0 + 32 * i + j;
                float v = __uint_as_float(r[j]) + bias[n];
                float g = 0.5f * v * (1.f + erff(v * 0.70710678118654752f));
                __nv_bfloat16 hi, lo;
                split2(g, &hi, &lo);
                sHi[mloc * 130 + 32 * i + j] = hi;
                sLo[mloc * 130 + 32 * i + j] = lo;
            }
        }
        __syncthreads();
        const uint32_t* sHi32 = (const uint32_t*)sHi;
        const uint32_t* sLo32 = (const uint32_t*)sLo;
        uint32_t* oHi32 = (uint32_t*)outHi;
        uint32_t* oLo32 = (uint32_t*)outLo;
        int halfN = N >> 1;
        for (int idx = tid; idx < 256 * 64; idx += 256) {
            int row = idx >> 6, c = idx & 63;
            size_t o = (size_t)(m0 + row) * halfN + (n0 >> 1) + c;
            oHi32[o] = sHi32[row * 65 + c];
            oLo32[o] = sLo32[row * 65 + c];
        }
    } else {
        float* sF = (float*)(smem + 1024);
#pragma unroll
        for (int i = 0; i < 4; i++) {
            uint32_t r[32];
            TC_LD_X32(r, cbase + 32 * i);
            TC_WAIT_LD();
#pragma unroll
            for (int j = 0; j < 32; j++)
                sF[mloc * 129 + 32 * i + j] = __uint_as_float(r[j]);
        }
        __syncthreads();
        for (int idx = tid; idx < 256 * 128; idx += 256) {
            int row = idx >> 7, c = idx & 127;
            size_t o = (size_t)(m0 + row) * N + n0 + c;
            outF[o] = sF[row * 129 + c] + bias[n0 + c] + resid[o];
        }
    }
    __syncthreads();
    if (wid == 0) TC_DEALLOC(tmem, 256);
#endif
}

// -------------------- host: tensor map construction --------------------------
typedef CUresult (*EncodeFn)(CUtensorMap*, CUtensorMapDataType, cuuint32_t, void*,
                             const cuuint64_t*, const cuuint64_t*, const cuuint32_t*,
                             const cuuint32_t*, CUtensorMapInterleave, CUtensorMapSwizzle,
                             CUtensorMapL2promotion, CUtensorMapFloatOOBfill);

static void makeMap(EncodeFn enc, CUtensorMap* m, void* ptr, uint64_t d0, uint64_t d1,
                    uint32_t boxRows) {
    cuuint64_t dims[2] = {d0, d1};
    cuuint64_t strides[1] = {d0 * 2};
    cuuint32_t box[2] = {64, boxRows};
    cuuint32_t es[2] = {1, 1};
    enc(m, CU_TENSOR_MAP_DATA_TYPE_BFLOAT16, 2, ptr, dims, strides, box, es,
        CU_TENSOR_MAP_INTERLEAVE_NONE, CU_TENSOR_MAP_SWIZZLE_128B,
        CU_TENSOR_MAP_L2_PROMOTION_L2_128B, CU_TENSOR_MAP_FLOAT_OOB_FILL_NONE);
}

// ---------------------------------------------------------------------------
extern "C" void kernel_launch(void* const* d_in, const int* in_sizes, int n_in,
                              void* d_out, int out_size) {
    const float* x    = (const float*)d_in[0];
    const float* n1g  = (const float*)d_in[1];
    const float* n1b  = (const float*)d_in[2];
    const float* w1   = (const float*)d_in[3];
    const float* w2   = (const float*)d_in[4];
    const float* b1   = (const float*)d_in[5];
    const float* b2   = (const float*)d_in[6];
    const float* n2g  = (const float*)d_in[7];
    const float* n2b  = (const float*)d_in[8];
    const float* fc1w = (const float*)d_in[9];
    const float* fc1b = (const float*)d_in[10];
    const float* fc2w = (const float*)d_in[11];
    const float* fc2b = (const float*)d_in[12];
    float* out = (float*)d_out;

    float *pT, *pP;
    cudaGetSymbolAddress((void**)&pT, g_T);
    cudaGetSymbolAddress((void**)&pP, g_P);
    void *pAh, *pAl, *pHh, *pHl, *pW1h, *pW1l, *pW2h, *pW2l;
    cudaGetSymbolAddress(&pAh, gA_hi);  cudaGetSymbolAddress(&pAl, gA_lo);
    cudaGetSymbolAddress(&pHh, gH_hi);  cudaGetSymbolAddress(&pHl, gH_lo);
    cudaGetSymbolAddress(&pW1h, gW1T_hi); cudaGetSymbolAddress(&pW1l, gW1T_lo);
    cudaGetSymbolAddress(&pW2h, gW2T_hi); cudaGetSymbolAddress(&pW2l, gW2T_lo);

    EncodeFn enc = nullptr;
    cudaDriverEntryPointQueryResult qr;
    cudaGetDriverEntryPoint("cuTensorMapEncodeTiled", (void**)&enc, cudaEnableDefault, &qr);

    CUtensorMap mAh, mAl, mW1h, mW1l, mHh, mHl, mW2h, mW2l;
    makeMap(enc, &mAh, pAh, Ddim, TOKENS, 256);
    makeMap(enc, &mAl, pAl, Ddim, TOKENS, 256);
    makeMap(enc, &mW1h, pW1h, Ddim, HIDv, 128);
    makeMap(enc, &mW1l, pW1l, Ddim, HIDv, 128);
    makeMap(enc, &mHh, pHh, HIDv, TOKENS, 256);
    makeMap(enc, &mHl, pHl, HIDv, TOKENS, 256);
    makeMap(enc, &mW2h, pW2h, HIDv, Ddim, 128);
    makeMap(enc, &mW2l, pW2l, HIDv, Ddim, 128);

    cudaFuncSetAttribute(k_gemm_tc<0>, cudaFuncAttributeMaxDynamicSharedMemorySize, GT_SMEM);
    cudaFuncSetAttribute(k_gemm_tc<1>, cudaFuncAttributeMaxDynamicSharedMemorySize, GT_SMEM);
    cudaFuncSetAttribute(k_fftW_tc, cudaFuncAttributeMaxDynamicSharedMemorySize, FWD_SMEM);
    cudaFuncSetAttribute(k_fftH_tc<0>, cudaFuncAttributeMaxDynamicSharedMemorySize, FH_SMEM);
    cudaFuncSetAttribute(k_fftH_tc<1>, cudaFuncAttributeMaxDynamicSharedMemorySize, FH_SMEM);
    cudaFuncSetAttribute(k_ifftW_tc, cudaFuncAttributeMaxDynamicSharedMemorySize, FW_SMEM);

    k_init<<<192, 256>>>();
    k_ln<0><<<TOKENS, 256>>>(x, n1g, n1b, pT, nullptr, nullptr);
    k_fftW_tc<<<dim3(6, 256), 256, FWD_SMEM>>>(pT);
    k_fftH_tc<0><<<dim3(6, 258), 256, FH_SMEM>>>();
    k_mix<1><<<dim3(1, 516, 8), 256>>>(w1, b1);
    k_mix<2><<<dim3(1, 516, 8), 256>>>(w2, b2);
    k_fftH_tc<1><<<dim3(6, 258), 256, FH_SMEM>>>();
    k_ifftW_tc<<<dim3(6, 256), 256, FW_SMEM>>>();
    k_ln<1><<<TOKENS, 256>>>(pP, n2g, n2b, nullptr,
                             (__nv_bfloat16*)pAh, (__nv_bfloat16*)pAl);
    dim3 tb(32, 8);
    k_splitT<<<dim3(HIDv / 32, Ddim / 32), tb>>>(fc1w, (__nv_bfloat16*)pW1h,
                                                 (__nv_bfloat16*)pW1l, Ddim, HIDv);
    k_splitT<<<dim3(Ddim / 32, HIDv / 32), tb>>>(fc2w, (__nv_bfloat16*)pW2h,
                                                 (__nv_bfloat16*)pW2l, HIDv, Ddim);
    k_gemm_tc<0><<<dim3(HIDv / 128, TOKENS / 256), 256, GT_SMEM>>>(
        mAh, mAl, mW1h, mW1l, fc1b, nullptr, nullptr,
        (__nv_bfloat16*)pHh, (__nv_bfloat16*)pHl, Ddim, HIDv);
    k_gemm_tc<1><<<dim3(Ddim / 128, TOKENS / 256), 256, GT_SMEM>>>(
        mHh, mHl, mW2h, mW2l, fc2b, x, out, nullptr, nullptr, HIDv, Ddim);
}